// round 6
// baseline (speedup 1.0000x reference)
#include <cuda_runtime.h>
#include <cuda_bf16.h>
#include <math.h>

#define NMAX 50000
#define EDGEMAX 300000
#define ETOT (EDGEMAX + NMAX)
#define GDIM 405
#define NB_SCAN 49

__device__ float g_t1  [NMAX * 256];
__device__ float g_henc[NMAX * 256];
__device__ float g_A   [NMAX * 1024];
__device__ float g_B   [NMAX * 1024];
__device__ float g_D   [NMAX * 192];
__device__ float g_E2  [NMAX * 192];
__device__ float g_G   [NMAX * 128];
__device__ float g_Hh  [NMAX * 128];
__device__ float g_asrc[NMAX * 4];
__device__ float g_adst[NMAX * 4];
__device__ int g_deg[NMAX];
__device__ int g_off[NMAX + 1];
__device__ int g_pos[NMAX];
__device__ int g_csr[ETOT];
__device__ int g_blk[64];
__device__ __nv_bfloat16 g_b1hi[NMAX * 1024];
__device__ __nv_bfloat16 g_b1lo[NMAX * 1024];
__device__ __nv_bfloat16 g_b2hi[NMAX * 1024];
__device__ __nv_bfloat16 g_b2lo[NMAX * 1024];
__device__ __nv_bfloat16 g_whi[1024 * 1024];
__device__ __nv_bfloat16 g_wlo[1024 * 1024];

__device__ __forceinline__ unsigned smem_u32(const void* p) {
    unsigned a;
    asm("{ .reg .u64 t; cvta.to.shared.u64 t, %1; cvt.u32.u64 %0, t; }"
        : "=r"(a) : "l"(p));
    return a;
}
__device__ __forceinline__ void cp16(unsigned d, const void* s, unsigned srcsz) {
    asm volatile("cp.async.cg.shared.global [%0], [%1], 16, %2;"
                 :: "r"(d), "l"(s), "r"(srcsz) : "memory");
}
__device__ __forceinline__ void cp_commit() {
    asm volatile("cp.async.commit_group;" ::: "memory");
}
__device__ __forceinline__ void ldsm4(unsigned r[4], unsigned addr) {
    asm volatile("ldmatrix.sync.aligned.m8n8.x4.shared.b16 {%0,%1,%2,%3}, [%4];"
                 : "=r"(r[0]), "=r"(r[1]), "=r"(r[2]), "=r"(r[3]) : "r"(addr));
}
__device__ __forceinline__ void mma16816(float c[4], const unsigned a[4],
                                         const unsigned b0, const unsigned b1) {
    asm volatile(
        "mma.sync.aligned.m16n8k16.row.col.f32.bf16.bf16.f32 "
        "{%0,%1,%2,%3}, {%4,%5,%6,%7}, {%8,%9}, {%0,%1,%2,%3};"
        : "+f"(c[0]), "+f"(c[1]), "+f"(c[2]), "+f"(c[3])
        : "r"(a[0]), "r"(a[1]), "r"(a[2]), "r"(a[3]), "r"(b0), "r"(b1));
}

__device__ __forceinline__ void split2(float v0, float v1,
                                       __nv_bfloat16* Hi, __nv_bfloat16* Lo,
                                       long long idx) {
    __nv_bfloat16 h0 = __float2bfloat16(v0);
    __nv_bfloat16 h1 = __float2bfloat16(v1);
    __nv_bfloat16 l0 = __float2bfloat16(v0 - __bfloat162float(h0));
    __nv_bfloat16 l1 = __float2bfloat16(v1 - __bfloat162float(h1));
    ushort2 uh; uh.x = __bfloat16_as_ushort(h0); uh.y = __bfloat16_as_ushort(h1);
    ushort2 ul; ul.x = __bfloat16_as_ushort(l0); ul.y = __bfloat16_as_ushort(l1);
    *(ushort2*)(Hi + idx) = uh;
    *(ushort2*)(Lo + idx) = ul;
}

__device__ __forceinline__ void split4(const float v[4],
                                       unsigned long long& hp, unsigned long long& lp) {
    unsigned long long h = 0, l = 0;
#pragma unroll
    for (int j = 0; j < 4; j++) {
        __nv_bfloat16 hb = __float2bfloat16(v[j]);
        __nv_bfloat16 lb = __float2bfloat16(v[j] - __bfloat162float(hb));
        h |= (unsigned long long)__bfloat16_as_ushort(hb) << (16 * j);
        l |= (unsigned long long)__bfloat16_as_ushort(lb) << (16 * j);
    }
    hp = h; lp = l;
}

__global__ void split_a_kernel(const float* __restrict__ X,
                               __nv_bfloat16* __restrict__ Hi,
                               __nv_bfloat16* __restrict__ Lo,
                               int M, int K, int Kpad)
{
    long long i = (long long)blockIdx.x * blockDim.x + threadIdx.x;
    long long tot = (long long)M * (Kpad >> 2);
    if (i >= tot) return;
    int k4 = (int)(i % (Kpad >> 2));
    long long row = i / (Kpad >> 2);
    float v[4];
#pragma unroll
    for (int j = 0; j < 4; j++) {
        int kk = 4 * k4 + j;
        v[j] = (kk < K) ? X[row * K + kk] : 0.f;
    }
    unsigned long long hp, lp;
    split4(v, hp, lp);
    *(unsigned long long*)(Hi + row * Kpad + 4 * k4) = hp;
    *(unsigned long long*)(Lo + row * Kpad + 4 * k4) = lp;
}

__global__ void split_bt_kernel(const float* __restrict__ B,
                                __nv_bfloat16* __restrict__ Hi,
                                __nv_bfloat16* __restrict__ Lo,
                                int K, int Nc, int Kpad)
{
    long long i = (long long)blockIdx.x * blockDim.x + threadIdx.x;
    long long tot = (long long)Nc * (Kpad >> 2);
    if (i >= tot) return;
    int n  = (int)(i % Nc);
    int k4 = (int)(i / Nc);
    float v[4];
#pragma unroll
    for (int j = 0; j < 4; j++) {
        int kk = 4 * k4 + j;
        v[j] = (kk < K) ? B[(long long)kk * Nc + n] : 0.f;
    }
    unsigned long long hp, lp;
    split4(v, hp, lp);
    *(unsigned long long*)(Hi + (long long)n * Kpad + 4 * k4) = hp;
    *(unsigned long long*)(Lo + (long long)n * Kpad + 4 * k4) = lp;
}

// ---------------------------------------------------------------------------
// Tensor-core GEMM (3-term bf16 split), cp.async depth-3 pipeline.
// act: 0 = (+bias), 1 = relu(+bias), 2 = elu(aggr+gat_bias)+acc+bias,
//      3 = fused MLP head: relu(v+bias) @ w2v + b2v -> outv [M,2]
// ---------------------------------------------------------------------------
#define ROWB 80
#define MATB (128 * ROWB)
#define OFF_AH 0
#define OFF_AL (1 * MATB)
#define OFF_BH (2 * MATB)
#define OFF_BL (3 * MATB)
#define BUFB (4 * MATB)
#define TC_SMEM (3 * BUFB)

__global__ __launch_bounds__(256)
void mma_gemm_kernel(const __nv_bfloat16* __restrict__ Ahi,
                     const __nv_bfloat16* __restrict__ Alo,
                     const __nv_bfloat16* __restrict__ Bhi,
                     const __nv_bfloat16* __restrict__ Blo,
                     float* __restrict__ Cf,
                     __nv_bfloat16* __restrict__ Chi,
                     __nv_bfloat16* __restrict__ Clo,
                     int M, int Nc, int Kpad,
                     const float* __restrict__ bias, int act,
                     const float* __restrict__ aggr,
                     const float* __restrict__ gat_bias,
                     const float* __restrict__ w2v,
                     const float* __restrict__ b2v,
                     float* __restrict__ outv)
{
    extern __shared__ char smem[];
    const unsigned sb = smem_u32(smem);
    const int tid = threadIdx.x;
    const int wid = tid >> 5, lane = tid & 31;
    const int bm = blockIdx.y * 128;
    const int bn = blockIdx.x * 128;
    const int Ntile = min(128, Nc - bn);
    const int warp_m = wid & 3;
    const int warp_n = wid >> 2;
    const int NCH = Kpad >> 5;

    float acc[2][8][4];
#pragma unroll
    for (int mi = 0; mi < 2; mi++)
#pragma unroll
        for (int ni = 0; ni < 8; ni++)
#pragma unroll
            for (int q = 0; q < 4; q++) acc[mi][ni][q] = 0.f;

    const int lrow = tid >> 1;
    const int lc0  = (tid & 1) * 2;

    const long long gmA = bm + lrow;
    const unsigned okA = (gmA < M) ? 16u : 0u;
    const long long rowA = (okA ? gmA : 0) * (long long)Kpad;
    const unsigned okB = (lrow < Ntile) ? 16u : 0u;
    const long long rowB = (long long)(okB ? (bn + lrow) : 0) * Kpad;

#define LOAD_CHUNK(c)                                                          \
    do {                                                                       \
        const unsigned bd = sb + ((c) % 3) * BUFB;                             \
        const long long kb = (long long)(c) * 32;                              \
        _Pragma("unroll")                                                      \
        for (int j = 0; j < 2; j++) {                                          \
            const int ch = lc0 + j;                                            \
            const unsigned so = lrow * ROWB + ch * 16;                         \
            const long long go = kb + ch * 8;                                  \
            cp16(bd + OFF_AH + so, Ahi + rowA + go, okA);                      \
            cp16(bd + OFF_AL + so, Alo + rowA + go, okA);                      \
            cp16(bd + OFF_BH + so, Bhi + rowB + go, okB);                      \
            cp16(bd + OFF_BL + so, Blo + rowB + go, okB);                      \
        }                                                                      \
    } while (0)

    LOAD_CHUNK(0);
    cp_commit();
    LOAD_CHUNK(1);
    cp_commit();

    for (int c = 0; c < NCH; c++) {
        if (c + 1 < NCH) {
            asm volatile("cp.async.wait_group 1;" ::: "memory");
        } else {
            asm volatile("cp.async.wait_group 0;" ::: "memory");
        }
        __syncthreads();
        if (c + 2 < NCH) {
            LOAD_CHUNK(c + 2);
            cp_commit();
        }

        const unsigned bd = sb + (c % 3) * BUFB;
#pragma unroll
        for (int ks = 0; ks < 2; ks++) {
            unsigned ah[2][4], al[2][4];
#pragma unroll
            for (int mi = 0; mi < 2; mi++) {
                const int row = warp_m * 32 + mi * 16 + (lane & 15);
                const int ch  = ks * 2 + (lane >> 4);
                const unsigned off = row * ROWB + ch * 16;
                ldsm4(ah[mi], bd + OFF_AH + off);
                ldsm4(al[mi], bd + OFF_AL + off);
            }
            unsigned bh[8][2], bl[8][2];
#pragma unroll
            for (int np = 0; np < 4; np++) {
                const int row = warp_n * 64 + np * 16 + ((lane >> 4) & 1) * 8 + (lane & 7);
                const int ch  = ks * 2 + ((lane >> 3) & 1);
                const unsigned off = row * ROWB + ch * 16;
                unsigned r[4];
                ldsm4(r, bd + OFF_BH + off);
                bh[2 * np][0] = r[0]; bh[2 * np][1] = r[1];
                bh[2 * np + 1][0] = r[2]; bh[2 * np + 1][1] = r[3];
                ldsm4(r, bd + OFF_BL + off);
                bl[2 * np][0] = r[0]; bl[2 * np][1] = r[1];
                bl[2 * np + 1][0] = r[2]; bl[2 * np + 1][1] = r[3];
            }
#pragma unroll
            for (int mi = 0; mi < 2; mi++)
#pragma unroll
                for (int ni = 0; ni < 8; ni++) {
                    mma16816(acc[mi][ni], ah[mi], bh[ni][0], bh[ni][1]);
                    mma16816(acc[mi][ni], ah[mi], bl[ni][0], bl[ni][1]);
                    mma16816(acc[mi][ni], al[mi], bh[ni][0], bh[ni][1]);
                }
        }
        __syncthreads();
    }

    // epilogue
#pragma unroll
    for (int mi = 0; mi < 2; mi++) {
#pragma unroll
        for (int half = 0; half < 2; half++) {
            const long long gm = bm + warp_m * 32 + mi * 16 + (lane >> 2) + half * 8;
            const bool rowok = gm < M;
            float s0 = 0.f, s1 = 0.f;
#pragma unroll
            for (int ni = 0; ni < 8; ni++) {
                const int gn = bn + warp_n * 64 + ni * 8 + (lane & 3) * 2;
                if (gn >= Nc) continue;
                float v0 = acc[mi][ni][2 * half + 0];
                float v1 = acc[mi][ni][2 * half + 1];
                if (act == 3) {
                    v0 = fmaxf(v0 + bias[gn], 0.f);
                    v1 = fmaxf(v1 + bias[gn + 1], 0.f);
                    s0 += v0 * w2v[gn * 2]     + v1 * w2v[(gn + 1) * 2];
                    s1 += v0 * w2v[gn * 2 + 1] + v1 * w2v[(gn + 1) * 2 + 1];
                    continue;
                }
                if (!rowok) continue;
                const long long gidx = gm * (long long)Nc + gn;
                if (act == 0) {
                    if (bias) { v0 += bias[gn]; v1 += bias[gn + 1]; }
                } else if (act == 1) {
                    v0 = fmaxf(v0 + bias[gn], 0.f);
                    v1 = fmaxf(v1 + bias[gn + 1], 0.f);
                } else {
                    float a0 = aggr[gidx]     + gat_bias[gn];
                    float a1 = aggr[gidx + 1] + gat_bias[gn + 1];
                    a0 = a0 > 0.f ? a0 : (expf(a0) - 1.f);
                    a1 = a1 > 0.f ? a1 : (expf(a1) - 1.f);
                    v0 = a0 + v0 + bias[gn];
                    v1 = a1 + v1 + bias[gn + 1];
                }
                if (Cf) { float2 o; o.x = v0; o.y = v1; *(float2*)(Cf + gidx) = o; }
                if (Chi) split2(v0, v1, Chi, Clo, gidx);
            }
            if (act == 3) {
                s0 += __shfl_xor_sync(0xffffffffu, s0, 1);
                s0 += __shfl_xor_sync(0xffffffffu, s0, 2);
                s1 += __shfl_xor_sync(0xffffffffu, s1, 1);
                s1 += __shfl_xor_sync(0xffffffffu, s1, 2);
                if (rowok && warp_n == 0 && (lane & 3) == 0) {
                    float2 o; o.x = s0 + b2v[0]; o.y = s1 + b2v[1];
                    *(float2*)(outv + gm * 2) = o;
                }
            }
        }
    }
}

// ---------------------------------------------------------------------------
// LayerNorm(256) + ReLU: one WARP per row, float4, shfl-only reductions.
// ---------------------------------------------------------------------------
__global__ __launch_bounds__(256)
void ln_relu_kernel(const float* __restrict__ x, const float* __restrict__ g,
                    const float* __restrict__ b,
                    __nv_bfloat16* __restrict__ Hi,
                    __nv_bfloat16* __restrict__ Lo, int N)
{
    const int row = blockIdx.x * 8 + (threadIdx.x >> 5);
    if (row >= N) return;
    const int lane = threadIdx.x & 31;
    const float4* p = (const float4*)(x + (long long)row * 256);
    float4 u0 = p[lane];
    float4 u1 = p[lane + 32];

    float s = u0.x + u0.y + u0.z + u0.w + u1.x + u1.y + u1.z + u1.w;
#pragma unroll
    for (int o = 16; o; o >>= 1) s += __shfl_xor_sync(0xffffffffu, s, o);
    const float m = s * (1.f / 256.f);

    float q = (u0.x - m) * (u0.x - m) + (u0.y - m) * (u0.y - m)
            + (u0.z - m) * (u0.z - m) + (u0.w - m) * (u0.w - m)
            + (u1.x - m) * (u1.x - m) + (u1.y - m) * (u1.y - m)
            + (u1.z - m) * (u1.z - m) + (u1.w - m) * (u1.w - m);
#pragma unroll
    for (int o = 16; o; o >>= 1) q += __shfl_xor_sync(0xffffffffu, q, o);
    const float inv = rsqrtf(q * (1.f / 256.f) + 1e-5f);

    const float4* gp = (const float4*)g;
    const float4* bp = (const float4*)b;
    float4 g0 = gp[lane], g1 = gp[lane + 32];
    float4 b0 = bp[lane], b1 = bp[lane + 32];

    float y[8];
    y[0] = fmaxf((u0.x - m) * inv * g0.x + b0.x, 0.f);
    y[1] = fmaxf((u0.y - m) * inv * g0.y + b0.y, 0.f);
    y[2] = fmaxf((u0.z - m) * inv * g0.z + b0.z, 0.f);
    y[3] = fmaxf((u0.w - m) * inv * g0.w + b0.w, 0.f);
    y[4] = fmaxf((u1.x - m) * inv * g1.x + b1.x, 0.f);
    y[5] = fmaxf((u1.y - m) * inv * g1.y + b1.y, 0.f);
    y[6] = fmaxf((u1.z - m) * inv * g1.z + b1.z, 0.f);
    y[7] = fmaxf((u1.w - m) * inv * g1.w + b1.w, 0.f);

#pragma unroll
    for (int grp = 0; grp < 2; grp++) {
        ushort4 h4, l4;
        unsigned short* hh = (unsigned short*)&h4;
        unsigned short* ll = (unsigned short*)&l4;
#pragma unroll
        for (int j = 0; j < 4; j++) {
            float v = y[grp * 4 + j];
            __nv_bfloat16 hb = __float2bfloat16(v);
            __nv_bfloat16 lb = __float2bfloat16(v - __bfloat162float(hb));
            hh[j] = __bfloat16_as_ushort(hb);
            ll[j] = __bfloat16_as_ushort(lb);
        }
        long long base = (long long)row * 256 + grp * 128 + 4 * lane;
        *(ushort4*)(Hi + base) = h4;
        *(ushort4*)(Lo + base) = l4;
    }
}

// ---------------------------------------------------------------------------
// CSR build
// ---------------------------------------------------------------------------
__global__ void deg_init_kernel(int* deg, int N)
{
    int i = blockIdx.x * blockDim.x + threadIdx.x;
    if (i < N) deg[i] = 1;
}
__global__ void deg_hist_kernel(const int* __restrict__ dst, int E, int* deg)
{
    int i = blockIdx.x * blockDim.x + threadIdx.x;
    if (i < E) atomicAdd(&deg[dst[i]], 1);
}
__global__ __launch_bounds__(1024)
void scan1_kernel(const int* __restrict__ deg, int* __restrict__ off,
                  int* __restrict__ blk, int N)
{
    __shared__ int sh[1024];
    int t = threadIdx.x;
    int i = blockIdx.x * 1024 + t;
    sh[t] = (i < N) ? deg[i] : 0;
    __syncthreads();
    for (int o = 1; o < 1024; o <<= 1) {
        int x = (t >= o) ? sh[t - o] : 0;
        __syncthreads();
        sh[t] += x;
        __syncthreads();
    }
    if (i < N) off[i + 1] = sh[t];
    if (t == 1023) blk[blockIdx.x] = sh[1023];
}
__global__ __launch_bounds__(64)
void scan2_kernel(int* blk, int nb)
{
    __shared__ int sh[64];
    int t = threadIdx.x;
    sh[t] = (t < nb) ? blk[t] : 0;
    __syncthreads();
    for (int o = 1; o < 64; o <<= 1) {
        int x = (t >= o) ? sh[t - o] : 0;
        __syncthreads();
        sh[t] += x;
        __syncthreads();
    }
    if (t < nb) blk[t] = sh[t];
}
__global__ void scan3_kernel(int* off, const int* __restrict__ blk, int N)
{
    int i = blockIdx.x * blockDim.x + threadIdx.x;
    if (i == 0) off[0] = 0;
    if (i < N) {
        int b = i >> 10;
        if (b > 0) off[i + 1] += blk[b - 1];
    }
}
__global__ void pos_init_kernel(const int* __restrict__ off, int* pos,
                                int* csr, int N)
{
    int i = blockIdx.x * blockDim.x + threadIdx.x;
    if (i < N) {
        int o = off[i];
        pos[i] = o + 1;
        csr[o] = i;
    }
}
__global__ void scatter_kernel(const int* __restrict__ src,
                               const int* __restrict__ dst, int E,
                               int* pos, int* csr)
{
    int i = blockIdx.x * blockDim.x + threadIdx.x;
    if (i < E) {
        int p = atomicAdd(&pos[dst[i]], 1);
        csr[p] = src[i];
    }
}

// ---------------------------------------------------------------------------
// Attention dot products (float4 vectorized)
// ---------------------------------------------------------------------------
__global__ __launch_bounds__(256)
void att_dots_kernel(const float* __restrict__ hW,
                     const float* __restrict__ att_src,
                     const float* __restrict__ att_dst,
                     float* __restrict__ asrc, float* __restrict__ adst,
                     int N, int H, int C)
{
    long long warp = ((long long)blockIdx.x * blockDim.x + threadIdx.x) >> 5;
    int lane = threadIdx.x & 31;
    if (warp >= (long long)N * H) return;
    int h = (int)(warp % H);
    const float4* hp = (const float4*)(hW + warp * C);
    const float4* as = (const float4*)(att_src + h * C);
    const float4* ad = (const float4*)(att_dst + h * C);
    const int C4 = C >> 2;
    float s = 0.f, d2 = 0.f;
    for (int c = lane; c < C4; c += 32) {
        float4 hv = hp[c];
        float4 a  = as[c];
        float4 d  = ad[c];
        s  += hv.x * a.x + hv.y * a.y + hv.z * a.z + hv.w * a.w;
        d2 += hv.x * d.x + hv.y * d.y + hv.z * d.z + hv.w * d.w;
    }
#pragma unroll
    for (int o = 16; o; o >>= 1) {
        s  += __shfl_down_sync(0xffffffffu, s, o);
        d2 += __shfl_down_sync(0xffffffffu, d2, o);
    }
    if (lane == 0) { asrc[warp] = s; adst[warp] = d2; }
}

// ---------------------------------------------------------------------------
// Fused GAT softmax-aggregate: one warp per (dst node, head), CSR neighbors.
// ---------------------------------------------------------------------------
__global__ __launch_bounds__(256)
void gat_aggr_csr_kernel(const int* __restrict__ off,
                         const int* __restrict__ csr,
                         const float* __restrict__ asrc,
                         const float* __restrict__ adst,
                         const float* __restrict__ hW,
                         float* __restrict__ out,
                         int N, int H, int C)
{
    long long warp = ((long long)blockIdx.x * blockDim.x + threadIdx.x) >> 5;
    const int lane = threadIdx.x & 31;
    if (warp >= (long long)N * H) return;
    const int n = (int)(warp / H);
    const int h = (int)(warp % H);
    const int beg = off[n], deg = off[n + 1] - beg;
    const float adv = adst[(long long)n * H + h];
    const int C4 = C >> 2;

    float mx = -INFINITY;
    for (int i = lane; i < deg; i += 32) {
        int s = csr[beg + i];
        float e = asrc[(long long)s * H + h] + adv;
        e = e > 0.f ? e : 0.2f * e;
        mx = fmaxf(mx, e);
    }
#pragma unroll
    for (int o = 16; o; o >>= 1)
        mx = fmaxf(mx, __shfl_xor_sync(0xffffffffu, mx, o));

    float den = 0.f;
    float4 a0 = make_float4(0.f, 0.f, 0.f, 0.f);
    float4 a1 = make_float4(0.f, 0.f, 0.f, 0.f);
    const bool g0 = lane < C4;
    const bool g1 = 32 + lane < C4;
    for (int i = 0; i < deg; i++) {
        int s = csr[beg + i];
        float e = asrc[(long long)s * H + h] + adv;
        e = e > 0.f ? e : 0.2f * e;
        float ee = expf(e - mx);
        den += ee;
        const float4* hp = (const float4*)(hW + ((long long)s * H + h) * C);
        if (g0) {
            float4 f = hp[lane];
            a0.x += ee * f.x; a0.y += ee * f.y; a0.z += ee * f.z; a0.w += ee * f.w;
        }
        if (g1) {
            float4 f = hp[32 + lane];
            a1.x += ee * f.x; a1.y += ee * f.y; a1.z += ee * f.z; a1.w += ee * f.w;
        }
    }
    float inv = 1.f / (den + 1e-16f);
    float4* op = (float4*)(out + ((long long)n * H + h) * C);
    if (g0) {
        a0.x *= inv; a0.y *= inv; a0.z *= inv; a0.w *= inv;
        op[lane] = a0;
    }
    if (g1) {
        a1.x *= inv; a1.y *= inv; a1.z *= inv; a1.w *= inv;
        op[32 + lane] = a1;
    }
}

// ---------------------------------------------------------------------------
// Host orchestration
// ---------------------------------------------------------------------------
static inline int kpad64(int k) { return (k + 63) & ~63; }

static inline void run_split_bt(const float* B, __nv_bfloat16* Hi, __nv_bfloat16* Lo,
                                int K, int Nc, int Kp)
{
    long long tot = (long long)Nc * (Kp >> 2);
    split_bt_kernel<<<(unsigned)((tot + 255) / 256), 256>>>(B, Hi, Lo, K, Nc, Kp);
}
static inline void run_gemm(const __nv_bfloat16* Ahi, const __nv_bfloat16* Alo,
                            const __nv_bfloat16* Bhi, const __nv_bfloat16* Blo,
                            float* Cf, __nv_bfloat16* Chi, __nv_bfloat16* Clo,
                            int M, int Nc, int Kp,
                            const float* bias, int act,
                            const float* aggr = nullptr,
                            const float* gat_bias = nullptr,
                            const float* w2v = nullptr,
                            const float* b2v = nullptr,
                            float* outv = nullptr)
{
    dim3 grid((Nc + 127) / 128, (M + 127) / 128);
    mma_gemm_kernel<<<grid, 256, TC_SMEM>>>(Ahi, Alo, Bhi, Blo, Cf, Chi, Clo,
                                            M, Nc, Kp, bias, act, aggr, gat_bias,
                                            w2v, b2v, outv);
}

static void run_gat(const int* off, const int* csr, int N, int H, int C,
                    const float* hW, const float* att_src, const float* att_dst,
                    float* asrc, float* adst, float* out)
{
    long long warps = (long long)N * H;
    long long blocks = (warps * 32 + 255) / 256;
    att_dots_kernel<<<(unsigned)blocks, 256>>>(hW, att_src, att_dst, asrc, adst, N, H, C);
    gat_aggr_csr_kernel<<<(unsigned)blocks, 256>>>(off, csr, asrc, adst, hW, out, N, H, C);
}

extern "C" void kernel_launch(void* const* d_in, const int* in_sizes, int n_in,
                              void* d_out, int out_size)
{
    const float* x      = (const float*)d_in[0];
    const int*   ei     = (const int*)d_in[1];
    const float* enc_w1 = (const float*)d_in[2];
    const float* enc_b1 = (const float*)d_in[3];
    const float* ln1_g  = (const float*)d_in[4];
    const float* ln1_b  = (const float*)d_in[5];
    const float* enc_w2 = (const float*)d_in[6];
    const float* enc_b2 = (const float*)d_in[7];
    const float* ln2_g  = (const float*)d_in[8];
    const float* ln2_b  = (const float*)d_in[9];
    const float* w1       = (const float*)d_in[10];
    const float* att_src1 = (const float*)d_in[11];
    const float* att_dst1 = (const float*)d_in[12];
    const float* bias1    = (const float*)d_in[13];
    const float* res1_w   = (const float*)d_in[14];
    const float* res1_b   = (const float*)d_in[15];
    const float* w2       = (const float*)d_in[16];
    const float* att_src2 = (const float*)d_in[17];
    const float* att_dst2 = (const float*)d_in[18];
    const float* bias2    = (const float*)d_in[19];
    const float* res2_w   = (const float*)d_in[20];
    const float* res2_b   = (const float*)d_in[21];
    const float* w3       = (const float*)d_in[22];
    const float* att_src3 = (const float*)d_in[23];
    const float* att_dst3 = (const float*)d_in[24];
    const float* bias3    = (const float*)d_in[25];
    const float* res3_w   = (const float*)d_in[26];
    const float* res3_b   = (const float*)d_in[27];
    const float* mlp_w1   = (const float*)d_in[28];
    const float* mlp_b1   = (const float*)d_in[29];
    const float* mlp_w2   = (const float*)d_in[30];
    const float* mlp_b2   = (const float*)d_in[31];

    const int N = in_sizes[0] / GDIM;
    const int E = in_sizes[1] / 2;
    const int* srcA = ei;
    const int* dstA = ei + E;

    cudaFuncSetAttribute(mma_gemm_kernel,
                         cudaFuncAttributeMaxDynamicSharedMemorySize, TC_SMEM);

    float *t1, *henc, *A, *B, *D, *E2, *G, *Hh, *asrc, *adst;
    int *deg, *off, *pos, *csr, *blk;
    __nv_bfloat16 *b1hi, *b1lo, *b2hi, *b2lo, *whi, *wlo;
    cudaGetSymbolAddress((void**)&t1,   g_t1);
    cudaGetSymbolAddress((void**)&henc, g_henc);
    cudaGetSymbolAddress((void**)&A,    g_A);
    cudaGetSymbolAddress((void**)&B,    g_B);
    cudaGetSymbolAddress((void**)&D,    g_D);
    cudaGetSymbolAddress((void**)&E2,   g_E2);
    cudaGetSymbolAddress((void**)&G,    g_G);
    cudaGetSymbolAddress((void**)&Hh,   g_Hh);
    cudaGetSymbolAddress((void**)&asrc, g_asrc);
    cudaGetSymbolAddress((void**)&adst, g_adst);
    cudaGetSymbolAddress((void**)&deg,  g_deg);
    cudaGetSymbolAddress((void**)&off,  g_off);
    cudaGetSymbolAddress((void**)&pos,  g_pos);
    cudaGetSymbolAddress((void**)&csr,  g_csr);
    cudaGetSymbolAddress((void**)&blk,  g_blk);
    cudaGetSymbolAddress((void**)&b1hi, g_b1hi);
    cudaGetSymbolAddress((void**)&b1lo, g_b1lo);
    cudaGetSymbolAddress((void**)&b2hi, g_b2hi);
    cudaGetSymbolAddress((void**)&b2lo, g_b2lo);
    cudaGetSymbolAddress((void**)&whi,  g_whi);
    cudaGetSymbolAddress((void**)&wlo,  g_wlo);

    // ---- CSR build ----
    deg_init_kernel<<<(N + 255) / 256, 256>>>(deg, N);
    deg_hist_kernel<<<(E + 255) / 256, 256>>>(dstA, E, deg);
    scan1_kernel<<<NB_SCAN, 1024>>>(deg, off, blk, N);
    scan2_kernel<<<1, 64>>>(blk, NB_SCAN);
    scan3_kernel<<<(N + 255) / 256, 256>>>(off, blk, N);
    pos_init_kernel<<<(N + 255) / 256, 256>>>(off, pos, csr, N);
    scatter_kernel<<<(E + 255) / 256, 256>>>(srcA, dstA, E, pos, csr);

    const unsigned lnb = (N + 7) / 8;

    // ---- JointEncoder ----
    {
        int Kp = kpad64(GDIM);   // 448
        long long tot = (long long)N * (Kp >> 2);
        split_a_kernel<<<(unsigned)((tot + 255) / 256), 256>>>(x, b1hi, b1lo, N, GDIM, Kp);
        run_split_bt(enc_w1, whi, wlo, GDIM, 256, Kp);
        run_gemm(b1hi, b1lo, whi, wlo, t1, nullptr, nullptr, N, 256, Kp, enc_b1, 0);
        ln_relu_kernel<<<lnb, 256>>>(t1, ln1_g, ln1_b, b2hi, b2lo, N);

        run_split_bt(enc_w2, whi, wlo, 256, 256, 256);
        run_gemm(b2hi, b2lo, whi, wlo, henc, nullptr, nullptr, N, 256, 256, enc_b2, 0);
        ln_relu_kernel<<<lnb, 256>>>(henc, ln2_g, ln2_b, b1hi, b1lo, N);
    }

    // ---- Block 1: GAT 256 -> 4x256 (concat) ----
    {
        run_split_bt(w1, whi, wlo, 256, 1024, 256);
        run_gemm(b1hi, b1lo, whi, wlo, A, nullptr, nullptr, N, 1024, 256, nullptr, 0); // hW1
        run_gat(off, csr, N, 4, 256, A, att_src1, att_dst1, asrc, adst, B);            // aggr1
        run_split_bt(res1_w, whi, wlo, 256, 1024, 256);
        run_gemm(b1hi, b1lo, whi, wlo, nullptr, b2hi, b2lo,
                 N, 1024, 256, res1_b, 2, B, bias1);                                   // h1 -> split
    }

    // ---- Block 2: GAT 1024 -> 2x96 (concat) ----
    {
        run_split_bt(w2, whi, wlo, 1024, 192, 1024);
        run_gemm(b2hi, b2lo, whi, wlo, D, nullptr, nullptr, N, 192, 1024, nullptr, 0); // hW2
        run_gat(off, csr, N, 2, 96, D, att_src2, att_dst2, asrc, adst, E2);            // aggr2
        run_split_bt(res2_w, whi, wlo, 1024, 192, 1024);
        run_gemm(b2hi, b2lo, whi, wlo, nullptr, b1hi, b1lo,
                 N, 192, 1024, res2_b, 2, E2, bias2);                                  // h2 -> split
    }

    // ---- Block 3: GAT 192 -> 1x128 (no concat) ----
    {
        run_split_bt(w3, whi, wlo, 192, 128, 192);
        run_gemm(b1hi, b1lo, whi, wlo, G, nullptr, nullptr, N, 128, 192, nullptr, 0);  // hW3
        run_gat(off, csr, N, 1, 128, G, att_src3, att_dst3, asrc, adst, Hh);           // aggr3
        run_split_bt(res3_w, whi, wlo, 192, 128, 192);
        run_gemm(b1hi, b1lo, whi, wlo, nullptr, b2hi, b2lo,
                 N, 128, 192, res3_b, 2, Hh, bias3);                                   // h3 -> split
    }

    // ---- MLP head: one GEMM, epilogue does relu + 64->2 projection ----
    {
        run_split_bt(mlp_w1, whi, wlo, 128, 64, 128);
        run_gemm(b2hi, b2lo, whi, wlo, nullptr, nullptr, nullptr,
                 N, 64, 128, mlp_b1, 3, nullptr, nullptr,
                 mlp_w2, mlp_b2, (float*)d_out);
    }
}

// round 7
// speedup vs baseline: 1.2687x; 1.2687x over previous
#include <cuda_runtime.h>
#include <cuda_bf16.h>
#include <math.h>

#define NMAX 50000
#define EDGEMAX 300000
#define ETOT (EDGEMAX + NMAX)
#define GDIM 405
#define NB_SCAN 49

__device__ float g_t1  [NMAX * 256];
__device__ float g_henc[NMAX * 256];
__device__ float g_A   [NMAX * 1024];
__device__ float g_B   [NMAX * 1024];
__device__ float g_D   [NMAX * 192];
__device__ float g_E2  [NMAX * 192];
__device__ float g_G   [NMAX * 128];
__device__ float g_Hh  [NMAX * 128];
__device__ float g_asrc[NMAX * 4];
__device__ float g_adst[NMAX * 4];
__device__ int g_deg[NMAX];
__device__ int g_off[NMAX + 1];
__device__ int g_pos[NMAX];
__device__ int g_csr[ETOT];
__device__ int g_blk[64];
__device__ __nv_bfloat16 g_b1hi[NMAX * 1024];
__device__ __nv_bfloat16 g_b1lo[NMAX * 1024];
__device__ __nv_bfloat16 g_b2hi[NMAX * 1024];
__device__ __nv_bfloat16 g_b2lo[NMAX * 1024];
__device__ __nv_bfloat16 g_whi[1024 * 1024];
__device__ __nv_bfloat16 g_wlo[1024 * 1024];

__device__ __forceinline__ unsigned smem_u32(const void* p) {
    unsigned a;
    asm("{ .reg .u64 t; cvta.to.shared.u64 t, %1; cvt.u32.u64 %0, t; }"
        : "=r"(a) : "l"(p));
    return a;
}
__device__ __forceinline__ void cp16(unsigned d, const void* s, unsigned srcsz) {
    asm volatile("cp.async.cg.shared.global [%0], [%1], 16, %2;"
                 :: "r"(d), "l"(s), "r"(srcsz) : "memory");
}
__device__ __forceinline__ void cp_commit() {
    asm volatile("cp.async.commit_group;" ::: "memory");
}
__device__ __forceinline__ void ldsm4(unsigned r[4], unsigned addr) {
    asm volatile("ldmatrix.sync.aligned.m8n8.x4.shared.b16 {%0,%1,%2,%3}, [%4];"
                 : "=r"(r[0]), "=r"(r[1]), "=r"(r[2]), "=r"(r[3]) : "r"(addr));
}
__device__ __forceinline__ void mma16816(float c[4], const unsigned a[4],
                                         const unsigned b0, const unsigned b1) {
    asm volatile(
        "mma.sync.aligned.m16n8k16.row.col.f32.bf16.bf16.f32 "
        "{%0,%1,%2,%3}, {%4,%5,%6,%7}, {%8,%9}, {%0,%1,%2,%3};"
        : "+f"(c[0]), "+f"(c[1]), "+f"(c[2]), "+f"(c[3])
        : "r"(a[0]), "r"(a[1]), "r"(a[2]), "r"(a[3]), "r"(b0), "r"(b1));
}

__device__ __forceinline__ void split2(float v0, float v1,
                                       __nv_bfloat16* Hi, __nv_bfloat16* Lo,
                                       long long idx) {
    __nv_bfloat16 h0 = __float2bfloat16(v0);
    __nv_bfloat16 h1 = __float2bfloat16(v1);
    __nv_bfloat16 l0 = __float2bfloat16(v0 - __bfloat162float(h0));
    __nv_bfloat16 l1 = __float2bfloat16(v1 - __bfloat162float(h1));
    ushort2 uh; uh.x = __bfloat16_as_ushort(h0); uh.y = __bfloat16_as_ushort(h1);
    ushort2 ul; ul.x = __bfloat16_as_ushort(l0); ul.y = __bfloat16_as_ushort(l1);
    *(ushort2*)(Hi + idx) = uh;
    *(ushort2*)(Lo + idx) = ul;
}

__device__ __forceinline__ void split4(const float v[4],
                                       unsigned long long& hp, unsigned long long& lp) {
    unsigned long long h = 0, l = 0;
#pragma unroll
    for (int j = 0; j < 4; j++) {
        __nv_bfloat16 hb = __float2bfloat16(v[j]);
        __nv_bfloat16 lb = __float2bfloat16(v[j] - __bfloat162float(hb));
        h |= (unsigned long long)__bfloat16_as_ushort(hb) << (16 * j);
        l |= (unsigned long long)__bfloat16_as_ushort(lb) << (16 * j);
    }
    hp = h; lp = l;
}

__global__ void split_a_kernel(const float* __restrict__ X,
                               __nv_bfloat16* __restrict__ Hi,
                               __nv_bfloat16* __restrict__ Lo,
                               int M, int K, int Kpad)
{
    long long i = (long long)blockIdx.x * blockDim.x + threadIdx.x;
    long long tot = (long long)M * (Kpad >> 2);
    if (i >= tot) return;
    int k4 = (int)(i % (Kpad >> 2));
    long long row = i / (Kpad >> 2);
    float v[4];
#pragma unroll
    for (int j = 0; j < 4; j++) {
        int kk = 4 * k4 + j;
        v[j] = (kk < K) ? X[row * K + kk] : 0.f;
    }
    unsigned long long hp, lp;
    split4(v, hp, lp);
    *(unsigned long long*)(Hi + row * Kpad + 4 * k4) = hp;
    *(unsigned long long*)(Lo + row * Kpad + 4 * k4) = lp;
}

__global__ void split_bt_kernel(const float* __restrict__ B,
                                __nv_bfloat16* __restrict__ Hi,
                                __nv_bfloat16* __restrict__ Lo,
                                int K, int Nc, int Kpad)
{
    long long i = (long long)blockIdx.x * blockDim.x + threadIdx.x;
    long long tot = (long long)Nc * (Kpad >> 2);
    if (i >= tot) return;
    int n  = (int)(i % Nc);
    int k4 = (int)(i / Nc);
    float v[4];
#pragma unroll
    for (int j = 0; j < 4; j++) {
        int kk = 4 * k4 + j;
        v[j] = (kk < K) ? B[(long long)kk * Nc + n] : 0.f;
    }
    unsigned long long hp, lp;
    split4(v, hp, lp);
    *(unsigned long long*)(Hi + (long long)n * Kpad + 4 * k4) = hp;
    *(unsigned long long*)(Lo + (long long)n * Kpad + 4 * k4) = lp;
}

// ---------------------------------------------------------------------------
// Tensor-core GEMM (3-term bf16 split), cp.async DOUBLE buffer (2 CTAs/SM).
// act: 0 = (+bias), 1 = relu(+bias), 2 = elu(aggr+gat_bias)+acc+bias,
//      3 = fused MLP head: relu(v+bias) @ w2v + b2v -> outv [M,2]
// ---------------------------------------------------------------------------
#define ROWB 80
#define MATB (128 * ROWB)
#define OFF_AH 0
#define OFF_AL (1 * MATB)
#define OFF_BH (2 * MATB)
#define OFF_BL (3 * MATB)
#define BUFB (4 * MATB)
#define TC_SMEM (2 * BUFB)     // 81920 -> 2 CTAs per SM

__global__ __launch_bounds__(256)
void mma_gemm_kernel(const __nv_bfloat16* __restrict__ Ahi,
                     const __nv_bfloat16* __restrict__ Alo,
                     const __nv_bfloat16* __restrict__ Bhi,
                     const __nv_bfloat16* __restrict__ Blo,
                     float* __restrict__ Cf,
                     __nv_bfloat16* __restrict__ Chi,
                     __nv_bfloat16* __restrict__ Clo,
                     int M, int Nc, int Kpad,
                     const float* __restrict__ bias, int act,
                     const float* __restrict__ aggr,
                     const float* __restrict__ gat_bias,
                     const float* __restrict__ w2v,
                     const float* __restrict__ b2v,
                     float* __restrict__ outv)
{
    extern __shared__ char smem[];
    const unsigned sb = smem_u32(smem);
    const int tid = threadIdx.x;
    const int wid = tid >> 5, lane = tid & 31;
    const int bm = blockIdx.y * 128;
    const int bn = blockIdx.x * 128;
    const int Ntile = min(128, Nc - bn);
    const int warp_m = wid & 3;
    const int warp_n = wid >> 2;
    const int NCH = Kpad >> 5;

    float acc[2][8][4];
#pragma unroll
    for (int mi = 0; mi < 2; mi++)
#pragma unroll
        for (int ni = 0; ni < 8; ni++)
#pragma unroll
            for (int q = 0; q < 4; q++) acc[mi][ni][q] = 0.f;

    const int lrow = tid >> 1;
    const int lc0  = (tid & 1) * 2;

    const long long gmA = bm + lrow;
    const unsigned okA = (gmA < M) ? 16u : 0u;
    const long long rowA = (okA ? gmA : 0) * (long long)Kpad;
    const unsigned okB = (lrow < Ntile) ? 16u : 0u;
    const long long rowB = (long long)(okB ? (bn + lrow) : 0) * Kpad;

#define LOAD_CHUNK(c)                                                          \
    do {                                                                       \
        const unsigned bd = sb + ((c) & 1) * BUFB;                             \
        const long long kb = (long long)(c) * 32;                              \
        _Pragma("unroll")                                                      \
        for (int j = 0; j < 2; j++) {                                          \
            const int ch = lc0 + j;                                            \
            const unsigned so = lrow * ROWB + ch * 16;                         \
            const long long go = kb + ch * 8;                                  \
            cp16(bd + OFF_AH + so, Ahi + rowA + go, okA);                      \
            cp16(bd + OFF_AL + so, Alo + rowA + go, okA);                      \
            cp16(bd + OFF_BH + so, Bhi + rowB + go, okB);                      \
            cp16(bd + OFF_BL + so, Blo + rowB + go, okB);                      \
        }                                                                      \
    } while (0)

    LOAD_CHUNK(0);
    cp_commit();

    for (int c = 0; c < NCH; c++) {
        if (c + 1 < NCH) {
            LOAD_CHUNK(c + 1);
            cp_commit();
            asm volatile("cp.async.wait_group 1;" ::: "memory");
        } else {
            asm volatile("cp.async.wait_group 0;" ::: "memory");
        }
        __syncthreads();

        const unsigned bd = sb + (c & 1) * BUFB;
#pragma unroll
        for (int ks = 0; ks < 2; ks++) {
            unsigned ah[2][4], al[2][4];
#pragma unroll
            for (int mi = 0; mi < 2; mi++) {
                const int row = warp_m * 32 + mi * 16 + (lane & 15);
                const int ch  = ks * 2 + (lane >> 4);
                const unsigned off = row * ROWB + ch * 16;
                ldsm4(ah[mi], bd + OFF_AH + off);
                ldsm4(al[mi], bd + OFF_AL + off);
            }
            unsigned bh[8][2], bl[8][2];
#pragma unroll
            for (int np = 0; np < 4; np++) {
                const int row = warp_n * 64 + np * 16 + ((lane >> 4) & 1) * 8 + (lane & 7);
                const int ch  = ks * 2 + ((lane >> 3) & 1);
                const unsigned off = row * ROWB + ch * 16;
                unsigned r[4];
                ldsm4(r, bd + OFF_BH + off);
                bh[2 * np][0] = r[0]; bh[2 * np][1] = r[1];
                bh[2 * np + 1][0] = r[2]; bh[2 * np + 1][1] = r[3];
                ldsm4(r, bd + OFF_BL + off);
                bl[2 * np][0] = r[0]; bl[2 * np][1] = r[1];
                bl[2 * np + 1][0] = r[2]; bl[2 * np + 1][1] = r[3];
            }
#pragma unroll
            for (int mi = 0; mi < 2; mi++)
#pragma unroll
                for (int ni = 0; ni < 8; ni++) {
                    mma16816(acc[mi][ni], ah[mi], bh[ni][0], bh[ni][1]);
                    mma16816(acc[mi][ni], ah[mi], bl[ni][0], bl[ni][1]);
                    mma16816(acc[mi][ni], al[mi], bh[ni][0], bh[ni][1]);
                }
        }
        __syncthreads();
    }

    // epilogue
#pragma unroll
    for (int mi = 0; mi < 2; mi++) {
#pragma unroll
        for (int half = 0; half < 2; half++) {
            const long long gm = bm + warp_m * 32 + mi * 16 + (lane >> 2) + half * 8;
            const bool rowok = gm < M;
            float s0 = 0.f, s1 = 0.f;
#pragma unroll
            for (int ni = 0; ni < 8; ni++) {
                const int gn = bn + warp_n * 64 + ni * 8 + (lane & 3) * 2;
                if (gn >= Nc) continue;
                float v0 = acc[mi][ni][2 * half + 0];
                float v1 = acc[mi][ni][2 * half + 1];
                if (act == 3) {
                    v0 = fmaxf(v0 + bias[gn], 0.f);
                    v1 = fmaxf(v1 + bias[gn + 1], 0.f);
                    s0 += v0 * w2v[gn * 2]     + v1 * w2v[(gn + 1) * 2];
                    s1 += v0 * w2v[gn * 2 + 1] + v1 * w2v[(gn + 1) * 2 + 1];
                    continue;
                }
                if (!rowok) continue;
                const long long gidx = gm * (long long)Nc + gn;
                if (act == 0) {
                    if (bias) { v0 += bias[gn]; v1 += bias[gn + 1]; }
                } else if (act == 1) {
                    v0 = fmaxf(v0 + bias[gn], 0.f);
                    v1 = fmaxf(v1 + bias[gn + 1], 0.f);
                } else {
                    float a0 = aggr[gidx]     + gat_bias[gn];
                    float a1 = aggr[gidx + 1] + gat_bias[gn + 1];
                    a0 = a0 > 0.f ? a0 : (expf(a0) - 1.f);
                    a1 = a1 > 0.f ? a1 : (expf(a1) - 1.f);
                    v0 = a0 + v0 + bias[gn];
                    v1 = a1 + v1 + bias[gn + 1];
                }
                if (Cf) { float2 o; o.x = v0; o.y = v1; *(float2*)(Cf + gidx) = o; }
                if (Chi) split2(v0, v1, Chi, Clo, gidx);
            }
            if (act == 3) {
                s0 += __shfl_xor_sync(0xffffffffu, s0, 1);
                s0 += __shfl_xor_sync(0xffffffffu, s0, 2);
                s1 += __shfl_xor_sync(0xffffffffu, s1, 1);
                s1 += __shfl_xor_sync(0xffffffffu, s1, 2);
                if (rowok && warp_n == 0 && (lane & 3) == 0) {
                    float2 o; o.x = s0 + b2v[0]; o.y = s1 + b2v[1];
                    *(float2*)(outv + gm * 2) = o;
                }
            }
        }
    }
}

// ---------------------------------------------------------------------------
// LayerNorm(256) + ReLU: one WARP per row, float4, shfl-only reductions.
// ---------------------------------------------------------------------------
__global__ __launch_bounds__(256)
void ln_relu_kernel(const float* __restrict__ x, const float* __restrict__ g,
                    const float* __restrict__ b,
                    __nv_bfloat16* __restrict__ Hi,
                    __nv_bfloat16* __restrict__ Lo, int N)
{
    const int row = blockIdx.x * 8 + (threadIdx.x >> 5);
    if (row >= N) return;
    const int lane = threadIdx.x & 31;
    const float4* p = (const float4*)(x + (long long)row * 256);
    float4 u0 = p[lane];
    float4 u1 = p[lane + 32];

    float s = u0.x + u0.y + u0.z + u0.w + u1.x + u1.y + u1.z + u1.w;
#pragma unroll
    for (int o = 16; o; o >>= 1) s += __shfl_xor_sync(0xffffffffu, s, o);
    const float m = s * (1.f / 256.f);

    float q = (u0.x - m) * (u0.x - m) + (u0.y - m) * (u0.y - m)
            + (u0.z - m) * (u0.z - m) + (u0.w - m) * (u0.w - m)
            + (u1.x - m) * (u1.x - m) + (u1.y - m) * (u1.y - m)
            + (u1.z - m) * (u1.z - m) + (u1.w - m) * (u1.w - m);
#pragma unroll
    for (int o = 16; o; o >>= 1) q += __shfl_xor_sync(0xffffffffu, q, o);
    const float inv = rsqrtf(q * (1.f / 256.f) + 1e-5f);

    const float4* gp = (const float4*)g;
    const float4* bp = (const float4*)b;
    float4 g0 = gp[lane], g1 = gp[lane + 32];
    float4 b0 = bp[lane], b1 = bp[lane + 32];

    float y[8];
    y[0] = fmaxf((u0.x - m) * inv * g0.x + b0.x, 0.f);
    y[1] = fmaxf((u0.y - m) * inv * g0.y + b0.y, 0.f);
    y[2] = fmaxf((u0.z - m) * inv * g0.z + b0.z, 0.f);
    y[3] = fmaxf((u0.w - m) * inv * g0.w + b0.w, 0.f);
    y[4] = fmaxf((u1.x - m) * inv * g1.x + b1.x, 0.f);
    y[5] = fmaxf((u1.y - m) * inv * g1.y + b1.y, 0.f);
    y[6] = fmaxf((u1.z - m) * inv * g1.z + b1.z, 0.f);
    y[7] = fmaxf((u1.w - m) * inv * g1.w + b1.w, 0.f);

#pragma unroll
    for (int grp = 0; grp < 2; grp++) {
        ushort4 h4, l4;
        unsigned short* hh = (unsigned short*)&h4;
        unsigned short* ll = (unsigned short*)&l4;
#pragma unroll
        for (int j = 0; j < 4; j++) {
            float v = y[grp * 4 + j];
            __nv_bfloat16 hb = __float2bfloat16(v);
            __nv_bfloat16 lb = __float2bfloat16(v - __bfloat162float(hb));
            hh[j] = __bfloat16_as_ushort(hb);
            ll[j] = __bfloat16_as_ushort(lb);
        }
        long long base = (long long)row * 256 + grp * 128 + 4 * lane;
        *(ushort4*)(Hi + base) = h4;
        *(ushort4*)(Lo + base) = l4;
    }
}

// ---------------------------------------------------------------------------
// CSR build
// ---------------------------------------------------------------------------
__global__ void deg_init_kernel(int* deg, int N)
{
    int i = blockIdx.x * blockDim.x + threadIdx.x;
    if (i < N) deg[i] = 1;
}
__global__ void deg_hist_kernel(const int* __restrict__ dst, int E, int* deg)
{
    int i = blockIdx.x * blockDim.x + threadIdx.x;
    if (i < E) atomicAdd(&deg[dst[i]], 1);
}
__global__ __launch_bounds__(1024)
void scan1_kernel(const int* __restrict__ deg, int* __restrict__ off,
                  int* __restrict__ blk, int N)
{
    __shared__ int sh[1024];
    int t = threadIdx.x;
    int i = blockIdx.x * 1024 + t;
    sh[t] = (i < N) ? deg[i] : 0;
    __syncthreads();
    for (int o = 1; o < 1024; o <<= 1) {
        int x = (t >= o) ? sh[t - o] : 0;
        __syncthreads();
        sh[t] += x;
        __syncthreads();
    }
    if (i < N) off[i + 1] = sh[t];
    if (t == 1023) blk[blockIdx.x] = sh[1023];
}
__global__ __launch_bounds__(64)
void scan2_kernel(int* blk, int nb)
{
    __shared__ int sh[64];
    int t = threadIdx.x;
    sh[t] = (t < nb) ? blk[t] : 0;
    __syncthreads();
    for (int o = 1; o < 64; o <<= 1) {
        int x = (t >= o) ? sh[t - o] : 0;
        __syncthreads();
        sh[t] += x;
        __syncthreads();
    }
    if (t < nb) blk[t] = sh[t];
}
__global__ void scan3_kernel(int* off, const int* __restrict__ blk, int N)
{
    int i = blockIdx.x * blockDim.x + threadIdx.x;
    if (i == 0) off[0] = 0;
    if (i < N) {
        int b = i >> 10;
        if (b > 0) off[i + 1] += blk[b - 1];
    }
}
__global__ void pos_init_kernel(const int* __restrict__ off, int* pos,
                                int* csr, int N)
{
    int i = blockIdx.x * blockDim.x + threadIdx.x;
    if (i < N) {
        int o = off[i];
        pos[i] = o + 1;
        csr[o] = i;
    }
}
__global__ void scatter_kernel(const int* __restrict__ src,
                               const int* __restrict__ dst, int E,
                               int* pos, int* csr)
{
    int i = blockIdx.x * blockDim.x + threadIdx.x;
    if (i < E) {
        int p = atomicAdd(&pos[dst[i]], 1);
        csr[p] = src[i];
    }
}

// ---------------------------------------------------------------------------
// Attention dot products (float4 vectorized)
// ---------------------------------------------------------------------------
__global__ __launch_bounds__(256)
void att_dots_kernel(const float* __restrict__ hW,
                     const float* __restrict__ att_src,
                     const float* __restrict__ att_dst,
                     float* __restrict__ asrc, float* __restrict__ adst,
                     int N, int H, int C)
{
    long long warp = ((long long)blockIdx.x * blockDim.x + threadIdx.x) >> 5;
    int lane = threadIdx.x & 31;
    if (warp >= (long long)N * H) return;
    int h = (int)(warp % H);
    const float4* hp = (const float4*)(hW + warp * C);
    const float4* as = (const float4*)(att_src + h * C);
    const float4* ad = (const float4*)(att_dst + h * C);
    const int C4 = C >> 2;
    float s = 0.f, d2 = 0.f;
    for (int c = lane; c < C4; c += 32) {
        float4 hv = hp[c];
        float4 a  = as[c];
        float4 d  = ad[c];
        s  += hv.x * a.x + hv.y * a.y + hv.z * a.z + hv.w * a.w;
        d2 += hv.x * d.x + hv.y * d.y + hv.z * d.z + hv.w * d.w;
    }
#pragma unroll
    for (int o = 16; o; o >>= 1) {
        s  += __shfl_down_sync(0xffffffffu, s, o);
        d2 += __shfl_down_sync(0xffffffffu, d2, o);
    }
    if (lane == 0) { asrc[warp] = s; adst[warp] = d2; }
}

// ---------------------------------------------------------------------------
// Fused GAT softmax-aggregate: one warp per (dst node, head), CSR neighbors.
// ---------------------------------------------------------------------------
__global__ __launch_bounds__(256)
void gat_aggr_csr_kernel(const int* __restrict__ off,
                         const int* __restrict__ csr,
                         const float* __restrict__ asrc,
                         const float* __restrict__ adst,
                         const float* __restrict__ hW,
                         float* __restrict__ out,
                         int N, int H, int C)
{
    long long warp = ((long long)blockIdx.x * blockDim.x + threadIdx.x) >> 5;
    const int lane = threadIdx.x & 31;
    if (warp >= (long long)N * H) return;
    const int n = (int)(warp / H);
    const int h = (int)(warp % H);
    const int beg = off[n], deg = off[n + 1] - beg;
    const float adv = adst[(long long)n * H + h];
    const int C4 = C >> 2;

    float mx = -INFINITY;
    for (int i = lane; i < deg; i += 32) {
        int s = csr[beg + i];
        float e = asrc[(long long)s * H + h] + adv;
        e = e > 0.f ? e : 0.2f * e;
        mx = fmaxf(mx, e);
    }
#pragma unroll
    for (int o = 16; o; o >>= 1)
        mx = fmaxf(mx, __shfl_xor_sync(0xffffffffu, mx, o));

    float den = 0.f;
    float4 a0 = make_float4(0.f, 0.f, 0.f, 0.f);
    float4 a1 = make_float4(0.f, 0.f, 0.f, 0.f);
    const bool g0 = lane < C4;
    const bool g1 = 32 + lane < C4;
    for (int i = 0; i < deg; i++) {
        int s = csr[beg + i];
        float e = asrc[(long long)s * H + h] + adv;
        e = e > 0.f ? e : 0.2f * e;
        float ee = expf(e - mx);
        den += ee;
        const float4* hp = (const float4*)(hW + ((long long)s * H + h) * C);
        if (g0) {
            float4 f = hp[lane];
            a0.x += ee * f.x; a0.y += ee * f.y; a0.z += ee * f.z; a0.w += ee * f.w;
        }
        if (g1) {
            float4 f = hp[32 + lane];
            a1.x += ee * f.x; a1.y += ee * f.y; a1.z += ee * f.z; a1.w += ee * f.w;
        }
    }
    float inv = 1.f / (den + 1e-16f);
    float4* op = (float4*)(out + ((long long)n * H + h) * C);
    if (g0) {
        a0.x *= inv; a0.y *= inv; a0.z *= inv; a0.w *= inv;
        op[lane] = a0;
    }
    if (g1) {
        a1.x *= inv; a1.y *= inv; a1.z *= inv; a1.w *= inv;
        op[32 + lane] = a1;
    }
}

// ---------------------------------------------------------------------------
// Host orchestration
// ---------------------------------------------------------------------------
static inline int kpad64(int k) { return (k + 63) & ~63; }

static inline void run_split_bt(const float* B, __nv_bfloat16* Hi, __nv_bfloat16* Lo,
                                int K, int Nc, int Kp)
{
    long long tot = (long long)Nc * (Kp >> 2);
    split_bt_kernel<<<(unsigned)((tot + 255) / 256), 256>>>(B, Hi, Lo, K, Nc, Kp);
}
static inline void run_gemm(const __nv_bfloat16* Ahi, const __nv_bfloat16* Alo,
                            const __nv_bfloat16* Bhi, const __nv_bfloat16* Blo,
                            float* Cf, __nv_bfloat16* Chi, __nv_bfloat16* Clo,
                            int M, int Nc, int Kp,
                            const float* bias, int act,
                            const float* aggr = nullptr,
                            const float* gat_bias = nullptr,
                            const float* w2v = nullptr,
                            const float* b2v = nullptr,
                            float* outv = nullptr)
{
    dim3 grid((Nc + 127) / 128, (M + 127) / 128);
    mma_gemm_kernel<<<grid, 256, TC_SMEM>>>(Ahi, Alo, Bhi, Blo, Cf, Chi, Clo,
                                            M, Nc, Kp, bias, act, aggr, gat_bias,
                                            w2v, b2v, outv);
}

static void run_gat(const int* off, const int* csr, int N, int H, int C,
                    const float* hW, const float* att_src, const float* att_dst,
                    float* asrc, float* adst, float* out)
{
    long long warps = (long long)N * H;
    long long blocks = (warps * 32 + 255) / 256;
    att_dots_kernel<<<(unsigned)blocks, 256>>>(hW, att_src, att_dst, asrc, adst, N, H, C);
    gat_aggr_csr_kernel<<<(unsigned)blocks, 256>>>(off, csr, asrc, adst, hW, out, N, H, C);
}

extern "C" void kernel_launch(void* const* d_in, const int* in_sizes, int n_in,
                              void* d_out, int out_size)
{
    const float* x      = (const float*)d_in[0];
    const int*   ei     = (const int*)d_in[1];
    const float* enc_w1 = (const float*)d_in[2];
    const float* enc_b1 = (const float*)d_in[3];
    const float* ln1_g  = (const float*)d_in[4];
    const float* ln1_b  = (const float*)d_in[5];
    const float* enc_w2 = (const float*)d_in[6];
    const float* enc_b2 = (const float*)d_in[7];
    const float* ln2_g  = (const float*)d_in[8];
    const float* ln2_b  = (const float*)d_in[9];
    const float* w1       = (const float*)d_in[10];
    const float* att_src1 = (const float*)d_in[11];
    const float* att_dst1 = (const float*)d_in[12];
    const float* bias1    = (const float*)d_in[13];
    const float* res1_w   = (const float*)d_in[14];
    const float* res1_b   = (const float*)d_in[15];
    const float* w2       = (const float*)d_in[16];
    const float* att_src2 = (const float*)d_in[17];
    const float* att_dst2 = (const float*)d_in[18];
    const float* bias2    = (const float*)d_in[19];
    const float* res2_w   = (const float*)d_in[20];
    const float* res2_b   = (const float*)d_in[21];
    const float* w3       = (const float*)d_in[22];
    const float* att_src3 = (const float*)d_in[23];
    const float* att_dst3 = (const float*)d_in[24];
    const float* bias3    = (const float*)d_in[25];
    const float* res3_w   = (const float*)d_in[26];
    const float* res3_b   = (const float*)d_in[27];
    const float* mlp_w1   = (const float*)d_in[28];
    const float* mlp_b1   = (const float*)d_in[29];
    const float* mlp_w2   = (const float*)d_in[30];
    const float* mlp_b2   = (const float*)d_in[31];

    const int N = in_sizes[0] / GDIM;
    const int E = in_sizes[1] / 2;
    const int* srcA = ei;
    const int* dstA = ei + E;

    cudaFuncSetAttribute(mma_gemm_kernel,
                         cudaFuncAttributeMaxDynamicSharedMemorySize, TC_SMEM);

    float *t1, *henc, *A, *B, *D, *E2, *G, *Hh, *asrc, *adst;
    int *deg, *off, *pos, *csr, *blk;
    __nv_bfloat16 *b1hi, *b1lo, *b2hi, *b2lo, *whi, *wlo;
    cudaGetSymbolAddress((void**)&t1,   g_t1);
    cudaGetSymbolAddress((void**)&henc, g_henc);
    cudaGetSymbolAddress((void**)&A,    g_A);
    cudaGetSymbolAddress((void**)&B,    g_B);
    cudaGetSymbolAddress((void**)&D,    g_D);
    cudaGetSymbolAddress((void**)&E2,   g_E2);
    cudaGetSymbolAddress((void**)&G,    g_G);
    cudaGetSymbolAddress((void**)&Hh,   g_Hh);
    cudaGetSymbolAddress((void**)&asrc, g_asrc);
    cudaGetSymbolAddress((void**)&adst, g_adst);
    cudaGetSymbolAddress((void**)&deg,  g_deg);
    cudaGetSymbolAddress((void**)&off,  g_off);
    cudaGetSymbolAddress((void**)&pos,  g_pos);
    cudaGetSymbolAddress((void**)&csr,  g_csr);
    cudaGetSymbolAddress((void**)&blk,  g_blk);
    cudaGetSymbolAddress((void**)&b1hi, g_b1hi);
    cudaGetSymbolAddress((void**)&b1lo, g_b1lo);
    cudaGetSymbolAddress((void**)&b2hi, g_b2hi);
    cudaGetSymbolAddress((void**)&b2lo, g_b2lo);
    cudaGetSymbolAddress((void**)&whi,  g_whi);
    cudaGetSymbolAddress((void**)&wlo,  g_wlo);

    // ---- CSR build ----
    deg_init_kernel<<<(N + 255) / 256, 256>>>(deg, N);
    deg_hist_kernel<<<(E + 255) / 256, 256>>>(dstA, E, deg);
    scan1_kernel<<<NB_SCAN, 1024>>>(deg, off, blk, N);
    scan2_kernel<<<1, 64>>>(blk, NB_SCAN);
    scan3_kernel<<<(N + 255) / 256, 256>>>(off, blk, N);
    pos_init_kernel<<<(N + 255) / 256, 256>>>(off, pos, csr, N);
    scatter_kernel<<<(E + 255) / 256, 256>>>(srcA, dstA, E, pos, csr);

    const unsigned lnb = (N + 7) / 8;

    // ---- JointEncoder ----
    {
        int Kp = kpad64(GDIM);   // 448
        long long tot = (long long)N * (Kp >> 2);
        split_a_kernel<<<(unsigned)((tot + 255) / 256), 256>>>(x, b1hi, b1lo, N, GDIM, Kp);
        run_split_bt(enc_w1, whi, wlo, GDIM, 256, Kp);
        run_gemm(b1hi, b1lo, whi, wlo, t1, nullptr, nullptr, N, 256, Kp, enc_b1, 0);
        ln_relu_kernel<<<lnb, 256>>>(t1, ln1_g, ln1_b, b2hi, b2lo, N);

        run_split_bt(enc_w2, whi, wlo, 256, 256, 256);
        run_gemm(b2hi, b2lo, whi, wlo, henc, nullptr, nullptr, N, 256, 256, enc_b2, 0);
        ln_relu_kernel<<<lnb, 256>>>(henc, ln2_g, ln2_b, b1hi, b1lo, N);
    }

    // ---- Block 1: GAT 256 -> 4x256 (concat) ----
    {
        run_split_bt(w1, whi, wlo, 256, 1024, 256);
        run_gemm(b1hi, b1lo, whi, wlo, A, nullptr, nullptr, N, 1024, 256, nullptr, 0); // hW1
        run_gat(off, csr, N, 4, 256, A, att_src1, att_dst1, asrc, adst, B);            // aggr1
        run_split_bt(res1_w, whi, wlo, 256, 1024, 256);
        run_gemm(b1hi, b1lo, whi, wlo, nullptr, b2hi, b2lo,
                 N, 1024, 256, res1_b, 2, B, bias1);                                   // h1 -> split
    }

    // ---- Block 2: GAT 1024 -> 2x96 (concat) ----
    {
        run_split_bt(w2, whi, wlo, 1024, 192, 1024);
        run_gemm(b2hi, b2lo, whi, wlo, D, nullptr, nullptr, N, 192, 1024, nullptr, 0); // hW2
        run_gat(off, csr, N, 2, 96, D, att_src2, att_dst2, asrc, adst, E2);            // aggr2
        run_split_bt(res2_w, whi, wlo, 1024, 192, 1024);
        run_gemm(b2hi, b2lo, whi, wlo, nullptr, b1hi, b1lo,
                 N, 192, 1024, res2_b, 2, E2, bias2);                                  // h2 -> split
    }

    // ---- Block 3: GAT 192 -> 1x128 (no concat) ----
    {
        run_split_bt(w3, whi, wlo, 192, 128, 192);
        run_gemm(b1hi, b1lo, whi, wlo, G, nullptr, nullptr, N, 128, 192, nullptr, 0);  // hW3
        run_gat(off, csr, N, 1, 128, G, att_src3, att_dst3, asrc, adst, Hh);           // aggr3
        run_split_bt(res3_w, whi, wlo, 192, 128, 192);
        run_gemm(b1hi, b1lo, whi, wlo, nullptr, b2hi, b2lo,
                 N, 128, 192, res3_b, 2, Hh, bias3);                                   // h3 -> split
    }

    // ---- MLP head: one GEMM, epilogue does relu + 64->2 projection ----
    {
        run_split_bt(mlp_w1, whi, wlo, 128, 64, 128);
        run_gemm(b2hi, b2lo, whi, wlo, nullptr, nullptr, nullptr,
                 N, 64, 128, mlp_b1, 3, nullptr, nullptr,
                 mlp_w2, mlp_b2, (float*)d_out);
    }
}

// round 8
// speedup vs baseline: 1.2765x; 1.0062x over previous
#include <cuda_runtime.h>
#include <cuda_bf16.h>
#include <math.h>

#define NMAX 50000
#define EDGEMAX 300000
#define ETOT (EDGEMAX + NMAX)
#define GDIM 405
#define NB_SCAN 49

__device__ float g_t1  [NMAX * 256];
__device__ float g_henc[NMAX * 256];
__device__ float g_A   [NMAX * 1024];
__device__ float g_B   [NMAX * 1024];
__device__ float g_D   [NMAX * 192];
__device__ float g_E2  [NMAX * 192];
__device__ float g_G   [NMAX * 128];
__device__ float g_Hh  [NMAX * 128];
__device__ float g_asrc[NMAX * 4];
__device__ float g_adst[NMAX * 4];
__device__ int g_deg[NMAX];
__device__ int g_off[NMAX + 1];
__device__ int g_pos[NMAX];
__device__ int g_csr[ETOT];
__device__ int g_blk[64];
__device__ __nv_bfloat16 g_b1hi[NMAX * 1024];
__device__ __nv_bfloat16 g_b1lo[NMAX * 1024];
__device__ __nv_bfloat16 g_b2hi[NMAX * 1024];
__device__ __nv_bfloat16 g_b2lo[NMAX * 1024];
__device__ __nv_bfloat16 g_whi[1024 * 1024];
__device__ __nv_bfloat16 g_wlo[1024 * 1024];

__device__ __forceinline__ unsigned smem_u32(const void* p) {
    unsigned a;
    asm("{ .reg .u64 t; cvta.to.shared.u64 t, %1; cvt.u32.u64 %0, t; }"
        : "=r"(a) : "l"(p));
    return a;
}
__device__ __forceinline__ void cp16(unsigned d, const void* s, unsigned srcsz) {
    asm volatile("cp.async.cg.shared.global [%0], [%1], 16, %2;"
                 :: "r"(d), "l"(s), "r"(srcsz) : "memory");
}
__device__ __forceinline__ void cp_commit() {
    asm volatile("cp.async.commit_group;" ::: "memory");
}
__device__ __forceinline__ void ldsm4(unsigned r[4], unsigned addr) {
    asm volatile("ldmatrix.sync.aligned.m8n8.x4.shared.b16 {%0,%1,%2,%3}, [%4];"
                 : "=r"(r[0]), "=r"(r[1]), "=r"(r[2]), "=r"(r[3]) : "r"(addr));
}
__device__ __forceinline__ void mma16816(float c[4], const unsigned a[4],
                                         const unsigned b0, const unsigned b1) {
    asm volatile(
        "mma.sync.aligned.m16n8k16.row.col.f32.bf16.bf16.f32 "
        "{%0,%1,%2,%3}, {%4,%5,%6,%7}, {%8,%9}, {%0,%1,%2,%3};"
        : "+f"(c[0]), "+f"(c[1]), "+f"(c[2]), "+f"(c[3])
        : "r"(a[0]), "r"(a[1]), "r"(a[2]), "r"(a[3]), "r"(b0), "r"(b1));
}

__device__ __forceinline__ void split2(float v0, float v1,
                                       __nv_bfloat16* Hi, __nv_bfloat16* Lo,
                                       long long idx) {
    __nv_bfloat16 h0 = __float2bfloat16(v0);
    __nv_bfloat16 h1 = __float2bfloat16(v1);
    __nv_bfloat16 l0 = __float2bfloat16(v0 - __bfloat162float(h0));
    __nv_bfloat16 l1 = __float2bfloat16(v1 - __bfloat162float(h1));
    ushort2 uh; uh.x = __bfloat16_as_ushort(h0); uh.y = __bfloat16_as_ushort(h1);
    ushort2 ul; ul.x = __bfloat16_as_ushort(l0); ul.y = __bfloat16_as_ushort(l1);
    *(ushort2*)(Hi + idx) = uh;
    *(ushort2*)(Lo + idx) = ul;
}

__device__ __forceinline__ void split4(const float v[4],
                                       unsigned long long& hp, unsigned long long& lp) {
    unsigned long long h = 0, l = 0;
#pragma unroll
    for (int j = 0; j < 4; j++) {
        __nv_bfloat16 hb = __float2bfloat16(v[j]);
        __nv_bfloat16 lb = __float2bfloat16(v[j] - __bfloat162float(hb));
        h |= (unsigned long long)__bfloat16_as_ushort(hb) << (16 * j);
        l |= (unsigned long long)__bfloat16_as_ushort(lb) << (16 * j);
    }
    hp = h; lp = l;
}

__global__ void split_a_kernel(const float* __restrict__ X,
                               __nv_bfloat16* __restrict__ Hi,
                               __nv_bfloat16* __restrict__ Lo,
                               int M, int K, int Kpad)
{
    long long i = (long long)blockIdx.x * blockDim.x + threadIdx.x;
    long long tot = (long long)M * (Kpad >> 2);
    if (i >= tot) return;
    int k4 = (int)(i % (Kpad >> 2));
    long long row = i / (Kpad >> 2);
    float v[4];
#pragma unroll
    for (int j = 0; j < 4; j++) {
        int kk = 4 * k4 + j;
        v[j] = (kk < K) ? X[row * K + kk] : 0.f;
    }
    unsigned long long hp, lp;
    split4(v, hp, lp);
    *(unsigned long long*)(Hi + row * Kpad + 4 * k4) = hp;
    *(unsigned long long*)(Lo + row * Kpad + 4 * k4) = lp;
}

__global__ void split_bt_kernel(const float* __restrict__ B,
                                __nv_bfloat16* __restrict__ Hi,
                                __nv_bfloat16* __restrict__ Lo,
                                int K, int Nc, int Kpad)
{
    long long i = (long long)blockIdx.x * blockDim.x + threadIdx.x;
    long long tot = (long long)Nc * (Kpad >> 2);
    if (i >= tot) return;
    int n  = (int)(i % Nc);
    int k4 = (int)(i / Nc);
    float v[4];
#pragma unroll
    for (int j = 0; j < 4; j++) {
        int kk = 4 * k4 + j;
        v[j] = (kk < K) ? B[(long long)kk * Nc + n] : 0.f;
    }
    unsigned long long hp, lp;
    split4(v, hp, lp);
    *(unsigned long long*)(Hi + (long long)n * Kpad + 4 * k4) = hp;
    *(unsigned long long*)(Lo + (long long)n * Kpad + 4 * k4) = lp;
}

// ---------------------------------------------------------------------------
// Tensor-core GEMM (3-term bf16 split), cp.async DOUBLE buffer (2 CTAs/SM).
// act: 0 = (+bias), 1 = relu(+bias), 2 = elu(aggr+gat_bias)+acc+bias,
//      3 = fused MLP head: relu(v+bias) @ w2v + b2v -> outv [M,2]
// ---------------------------------------------------------------------------
#define ROWB 80
#define MATB (128 * ROWB)
#define OFF_AH 0
#define OFF_AL (1 * MATB)
#define OFF_BH (2 * MATB)
#define OFF_BL (3 * MATB)
#define BUFB (4 * MATB)
#define TC_SMEM (2 * BUFB)     // 81920 -> 2 CTAs per SM

__global__ __launch_bounds__(256)
void mma_gemm_kernel(const __nv_bfloat16* __restrict__ Ahi,
                     const __nv_bfloat16* __restrict__ Alo,
                     const __nv_bfloat16* __restrict__ Bhi,
                     const __nv_bfloat16* __restrict__ Blo,
                     float* __restrict__ Cf,
                     __nv_bfloat16* __restrict__ Chi,
                     __nv_bfloat16* __restrict__ Clo,
                     int M, int Nc, int Kpad,
                     const float* __restrict__ bias, int act,
                     const float* __restrict__ aggr,
                     const float* __restrict__ gat_bias,
                     const float* __restrict__ w2v,
                     const float* __restrict__ b2v,
                     float* __restrict__ outv)
{
    extern __shared__ char smem[];
    const unsigned sb = smem_u32(smem);
    const int tid = threadIdx.x;
    const int wid = tid >> 5, lane = tid & 31;
    const int bm = blockIdx.y * 128;
    const int bn = blockIdx.x * 128;
    const int Ntile = min(128, Nc - bn);
    const int warp_m = wid & 3;
    const int warp_n = wid >> 2;
    const int NCH = Kpad >> 5;

    float acc[2][8][4];
#pragma unroll
    for (int mi = 0; mi < 2; mi++)
#pragma unroll
        for (int ni = 0; ni < 8; ni++)
#pragma unroll
            for (int q = 0; q < 4; q++) acc[mi][ni][q] = 0.f;

    const int lrow = tid >> 1;
    const int lc0  = (tid & 1) * 2;

    const long long gmA = bm + lrow;
    const unsigned okA = (gmA < M) ? 16u : 0u;
    const long long rowA = (okA ? gmA : 0) * (long long)Kpad;
    const unsigned okB = (lrow < Ntile) ? 16u : 0u;
    const long long rowB = (long long)(okB ? (bn + lrow) : 0) * Kpad;

#define LOAD_CHUNK(c)                                                          \
    do {                                                                       \
        const unsigned bd = sb + ((c) & 1) * BUFB;                             \
        const long long kb = (long long)(c) * 32;                              \
        _Pragma("unroll")                                                      \
        for (int j = 0; j < 2; j++) {                                          \
            const int ch = lc0 + j;                                            \
            const unsigned so = lrow * ROWB + ch * 16;                         \
            const long long go = kb + ch * 8;                                  \
            cp16(bd + OFF_AH + so, Ahi + rowA + go, okA);                      \
            cp16(bd + OFF_AL + so, Alo + rowA + go, okA);                      \
            cp16(bd + OFF_BH + so, Bhi + rowB + go, okB);                      \
            cp16(bd + OFF_BL + so, Blo + rowB + go, okB);                      \
        }                                                                      \
    } while (0)

    LOAD_CHUNK(0);
    cp_commit();

    for (int c = 0; c < NCH; c++) {
        if (c + 1 < NCH) {
            LOAD_CHUNK(c + 1);
            cp_commit();
            asm volatile("cp.async.wait_group 1;" ::: "memory");
        } else {
            asm volatile("cp.async.wait_group 0;" ::: "memory");
        }
        __syncthreads();

        const unsigned bd = sb + (c & 1) * BUFB;
#pragma unroll
        for (int ks = 0; ks < 2; ks++) {
            unsigned ah[2][4], al[2][4];
#pragma unroll
            for (int mi = 0; mi < 2; mi++) {
                const int row = warp_m * 32 + mi * 16 + (lane & 15);
                const int ch  = ks * 2 + (lane >> 4);
                const unsigned off = row * ROWB + ch * 16;
                ldsm4(ah[mi], bd + OFF_AH + off);
                ldsm4(al[mi], bd + OFF_AL + off);
            }
            unsigned bh[8][2], bl[8][2];
#pragma unroll
            for (int np = 0; np < 4; np++) {
                const int row = warp_n * 64 + np * 16 + ((lane >> 4) & 1) * 8 + (lane & 7);
                const int ch  = ks * 2 + ((lane >> 3) & 1);
                const unsigned off = row * ROWB + ch * 16;
                unsigned r[4];
                ldsm4(r, bd + OFF_BH + off);
                bh[2 * np][0] = r[0]; bh[2 * np][1] = r[1];
                bh[2 * np + 1][0] = r[2]; bh[2 * np + 1][1] = r[3];
                ldsm4(r, bd + OFF_BL + off);
                bl[2 * np][0] = r[0]; bl[2 * np][1] = r[1];
                bl[2 * np + 1][0] = r[2]; bl[2 * np + 1][1] = r[3];
            }
#pragma unroll
            for (int mi = 0; mi < 2; mi++)
#pragma unroll
                for (int ni = 0; ni < 8; ni++) {
                    mma16816(acc[mi][ni], ah[mi], bh[ni][0], bh[ni][1]);
                    mma16816(acc[mi][ni], ah[mi], bl[ni][0], bl[ni][1]);
                    mma16816(acc[mi][ni], al[mi], bh[ni][0], bh[ni][1]);
                }
        }
        __syncthreads();
    }

    // epilogue
#pragma unroll
    for (int mi = 0; mi < 2; mi++) {
#pragma unroll
        for (int half = 0; half < 2; half++) {
            const long long gm = bm + warp_m * 32 + mi * 16 + (lane >> 2) + half * 8;
            const bool rowok = gm < M;
            float s0 = 0.f, s1 = 0.f;
#pragma unroll
            for (int ni = 0; ni < 8; ni++) {
                const int gn = bn + warp_n * 64 + ni * 8 + (lane & 3) * 2;
                if (gn >= Nc) continue;
                float v0 = acc[mi][ni][2 * half + 0];
                float v1 = acc[mi][ni][2 * half + 1];
                if (act == 3) {
                    v0 = fmaxf(v0 + bias[gn], 0.f);
                    v1 = fmaxf(v1 + bias[gn + 1], 0.f);
                    s0 += v0 * w2v[gn * 2]     + v1 * w2v[(gn + 1) * 2];
                    s1 += v0 * w2v[gn * 2 + 1] + v1 * w2v[(gn + 1) * 2 + 1];
                    continue;
                }
                if (!rowok) continue;
                const long long gidx = gm * (long long)Nc + gn;
                if (act == 0) {
                    if (bias) { v0 += bias[gn]; v1 += bias[gn + 1]; }
                } else if (act == 1) {
                    v0 = fmaxf(v0 + bias[gn], 0.f);
                    v1 = fmaxf(v1 + bias[gn + 1], 0.f);
                } else {
                    float a0 = aggr[gidx]     + gat_bias[gn];
                    float a1 = aggr[gidx + 1] + gat_bias[gn + 1];
                    a0 = a0 > 0.f ? a0 : (expf(a0) - 1.f);
                    a1 = a1 > 0.f ? a1 : (expf(a1) - 1.f);
                    v0 = a0 + v0 + bias[gn];
                    v1 = a1 + v1 + bias[gn + 1];
                }
                if (Cf) { float2 o; o.x = v0; o.y = v1; *(float2*)(Cf + gidx) = o; }
                if (Chi) split2(v0, v1, Chi, Clo, gidx);
            }
            if (act == 3) {
                s0 += __shfl_xor_sync(0xffffffffu, s0, 1);
                s0 += __shfl_xor_sync(0xffffffffu, s0, 2);
                s1 += __shfl_xor_sync(0xffffffffu, s1, 1);
                s1 += __shfl_xor_sync(0xffffffffu, s1, 2);
                if (rowok && warp_n == 0 && (lane & 3) == 0) {
                    float2 o; o.x = s0 + b2v[0]; o.y = s1 + b2v[1];
                    *(float2*)(outv + gm * 2) = o;
                }
            }
        }
    }
}

// ---------------------------------------------------------------------------
// LayerNorm(256) + ReLU: one WARP per row, float4, shfl-only reductions.
// ---------------------------------------------------------------------------
__global__ __launch_bounds__(256)
void ln_relu_kernel(const float* __restrict__ x, const float* __restrict__ g,
                    const float* __restrict__ b,
                    __nv_bfloat16* __restrict__ Hi,
                    __nv_bfloat16* __restrict__ Lo, int N)
{
    const int row = blockIdx.x * 8 + (threadIdx.x >> 5);
    if (row >= N) return;
    const int lane = threadIdx.x & 31;
    const float4* p = (const float4*)(x + (long long)row * 256);
    float4 u0 = p[lane];
    float4 u1 = p[lane + 32];

    float s = u0.x + u0.y + u0.z + u0.w + u1.x + u1.y + u1.z + u1.w;
#pragma unroll
    for (int o = 16; o; o >>= 1) s += __shfl_xor_sync(0xffffffffu, s, o);
    const float m = s * (1.f / 256.f);

    float q = (u0.x - m) * (u0.x - m) + (u0.y - m) * (u0.y - m)
            + (u0.z - m) * (u0.z - m) + (u0.w - m) * (u0.w - m)
            + (u1.x - m) * (u1.x - m) + (u1.y - m) * (u1.y - m)
            + (u1.z - m) * (u1.z - m) + (u1.w - m) * (u1.w - m);
#pragma unroll
    for (int o = 16; o; o >>= 1) q += __shfl_xor_sync(0xffffffffu, q, o);
    const float inv = rsqrtf(q * (1.f / 256.f) + 1e-5f);

    const float4* gp = (const float4*)g;
    const float4* bp = (const float4*)b;
    float4 g0 = gp[lane], g1 = gp[lane + 32];
    float4 b0 = bp[lane], b1 = bp[lane + 32];

    float y[8];
    y[0] = fmaxf((u0.x - m) * inv * g0.x + b0.x, 0.f);
    y[1] = fmaxf((u0.y - m) * inv * g0.y + b0.y, 0.f);
    y[2] = fmaxf((u0.z - m) * inv * g0.z + b0.z, 0.f);
    y[3] = fmaxf((u0.w - m) * inv * g0.w + b0.w, 0.f);
    y[4] = fmaxf((u1.x - m) * inv * g1.x + b1.x, 0.f);
    y[5] = fmaxf((u1.y - m) * inv * g1.y + b1.y, 0.f);
    y[6] = fmaxf((u1.z - m) * inv * g1.z + b1.z, 0.f);
    y[7] = fmaxf((u1.w - m) * inv * g1.w + b1.w, 0.f);

#pragma unroll
    for (int grp = 0; grp < 2; grp++) {
        ushort4 h4, l4;
        unsigned short* hh = (unsigned short*)&h4;
        unsigned short* ll = (unsigned short*)&l4;
#pragma unroll
        for (int j = 0; j < 4; j++) {
            float v = y[grp * 4 + j];
            __nv_bfloat16 hb = __float2bfloat16(v);
            __nv_bfloat16 lb = __float2bfloat16(v - __bfloat162float(hb));
            hh[j] = __bfloat16_as_ushort(hb);
            ll[j] = __bfloat16_as_ushort(lb);
        }
        long long base = (long long)row * 256 + grp * 128 + 4 * lane;
        *(ushort4*)(Hi + base) = h4;
        *(ushort4*)(Lo + base) = l4;
    }
}

// ---------------------------------------------------------------------------
// CSR build
// ---------------------------------------------------------------------------
__global__ void deg_init_kernel(int* deg, int N)
{
    int i = blockIdx.x * blockDim.x + threadIdx.x;
    if (i < N) deg[i] = 1;
}
__global__ void deg_hist_kernel(const int* __restrict__ dst, int E, int* deg)
{
    int i = blockIdx.x * blockDim.x + threadIdx.x;
    if (i < E) atomicAdd(&deg[dst[i]], 1);
}
__global__ __launch_bounds__(1024)
void scan1_kernel(const int* __restrict__ deg, int* __restrict__ off,
                  int* __restrict__ blk, int N)
{
    __shared__ int sh[1024];
    int t = threadIdx.x;
    int i = blockIdx.x * 1024 + t;
    sh[t] = (i < N) ? deg[i] : 0;
    __syncthreads();
    for (int o = 1; o < 1024; o <<= 1) {
        int x = (t >= o) ? sh[t - o] : 0;
        __syncthreads();
        sh[t] += x;
        __syncthreads();
    }
    if (i < N) off[i + 1] = sh[t];
    if (t == 1023) blk[blockIdx.x] = sh[1023];
}
__global__ __launch_bounds__(64)
void scan2_kernel(int* blk, int nb)
{
    __shared__ int sh[64];
    int t = threadIdx.x;
    sh[t] = (t < nb) ? blk[t] : 0;
    __syncthreads();
    for (int o = 1; o < 64; o <<= 1) {
        int x = (t >= o) ? sh[t - o] : 0;
        __syncthreads();
        sh[t] += x;
        __syncthreads();
    }
    if (t < nb) blk[t] = sh[t];
}
__global__ void scan3_kernel(int* off, const int* __restrict__ blk, int N)
{
    int i = blockIdx.x * blockDim.x + threadIdx.x;
    if (i == 0) off[0] = 0;
    if (i < N) {
        int b = i >> 10;
        if (b > 0) off[i + 1] += blk[b - 1];
    }
}
__global__ void pos_init_kernel(const int* __restrict__ off, int* pos,
                                int* csr, int N)
{
    int i = blockIdx.x * blockDim.x + threadIdx.x;
    if (i < N) {
        int o = off[i];
        pos[i] = o + 1;
        csr[o] = i;
    }
}
__global__ void scatter_kernel(const int* __restrict__ src,
                               const int* __restrict__ dst, int E,
                               int* pos, int* csr)
{
    int i = blockIdx.x * blockDim.x + threadIdx.x;
    if (i < E) {
        int p = atomicAdd(&pos[dst[i]], 1);
        csr[p] = src[i];
    }
}

// ---------------------------------------------------------------------------
// Attention dot products (float4 vectorized)
// ---------------------------------------------------------------------------
__global__ __launch_bounds__(256)
void att_dots_kernel(const float* __restrict__ hW,
                     const float* __restrict__ att_src,
                     const float* __restrict__ att_dst,
                     float* __restrict__ asrc, float* __restrict__ adst,
                     int N, int H, int C)
{
    long long warp = ((long long)blockIdx.x * blockDim.x + threadIdx.x) >> 5;
    int lane = threadIdx.x & 31;
    if (warp >= (long long)N * H) return;
    int h = (int)(warp % H);
    const float4* hp = (const float4*)(hW + warp * C);
    const float4* as = (const float4*)(att_src + h * C);
    const float4* ad = (const float4*)(att_dst + h * C);
    const int C4 = C >> 2;
    float s = 0.f, d2 = 0.f;
    for (int c = lane; c < C4; c += 32) {
        float4 hv = hp[c];
        float4 a  = as[c];
        float4 d  = ad[c];
        s  += hv.x * a.x + hv.y * a.y + hv.z * a.z + hv.w * a.w;
        d2 += hv.x * d.x + hv.y * d.y + hv.z * d.z + hv.w * d.w;
    }
#pragma unroll
    for (int o = 16; o; o >>= 1) {
        s  += __shfl_down_sync(0xffffffffu, s, o);
        d2 += __shfl_down_sync(0xffffffffu, d2, o);
    }
    if (lane == 0) { asrc[warp] = s; adst[warp] = d2; }
}

// ---------------------------------------------------------------------------
// Fused GAT softmax-aggregate: one warp per (dst node, head), CSR neighbors.
// ---------------------------------------------------------------------------
__global__ __launch_bounds__(256)
void gat_aggr_csr_kernel(const int* __restrict__ off,
                         const int* __restrict__ csr,
                         const float* __restrict__ asrc,
                         const float* __restrict__ adst,
                         const float* __restrict__ hW,
                         float* __restrict__ out,
                         int N, int H, int C)
{
    long long warp = ((long long)blockIdx.x * blockDim.x + threadIdx.x) >> 5;
    const int lane = threadIdx.x & 31;
    if (warp >= (long long)N * H) return;
    const int n = (int)(warp / H);
    const int h = (int)(warp % H);
    const int beg = off[n], deg = off[n + 1] - beg;
    const float adv = adst[(long long)n * H + h];
    const int C4 = C >> 2;

    float mx = -INFINITY;
    for (int i = lane; i < deg; i += 32) {
        int s = csr[beg + i];
        float e = asrc[(long long)s * H + h] + adv;
        e = e > 0.f ? e : 0.2f * e;
        mx = fmaxf(mx, e);
    }
#pragma unroll
    for (int o = 16; o; o >>= 1)
        mx = fmaxf(mx, __shfl_xor_sync(0xffffffffu, mx, o));

    float den = 0.f;
    float4 a0 = make_float4(0.f, 0.f, 0.f, 0.f);
    float4 a1 = make_float4(0.f, 0.f, 0.f, 0.f);
    const bool g0 = lane < C4;
    const bool g1 = 32 + lane < C4;
    for (int i = 0; i < deg; i++) {
        int s = csr[beg + i];
        float e = asrc[(long long)s * H + h] + adv;
        e = e > 0.f ? e : 0.2f * e;
        float ee = expf(e - mx);
        den += ee;
        const float4* hp = (const float4*)(hW + ((long long)s * H + h) * C);
        if (g0) {
            float4 f = hp[lane];
            a0.x += ee * f.x; a0.y += ee * f.y; a0.z += ee * f.z; a0.w += ee * f.w;
        }
        if (g1) {
            float4 f = hp[32 + lane];
            a1.x += ee * f.x; a1.y += ee * f.y; a1.z += ee * f.z; a1.w += ee * f.w;
        }
    }
    float inv = 1.f / (den + 1e-16f);
    float4* op = (float4*)(out + ((long long)n * H + h) * C);
    if (g0) {
        a0.x *= inv; a0.y *= inv; a0.z *= inv; a0.w *= inv;
        op[lane] = a0;
    }
    if (g1) {
        a1.x *= inv; a1.y *= inv; a1.z *= inv; a1.w *= inv;
        op[32 + lane] = a1;
    }
}

// ---------------------------------------------------------------------------
// Host orchestration
// ---------------------------------------------------------------------------
static inline int kpad64(int k) { return (k + 63) & ~63; }

static inline void run_split_bt(const float* B, __nv_bfloat16* Hi, __nv_bfloat16* Lo,
                                int K, int Nc, int Kp)
{
    long long tot = (long long)Nc * (Kp >> 2);
    split_bt_kernel<<<(unsigned)((tot + 255) / 256), 256>>>(B, Hi, Lo, K, Nc, Kp);
}
static inline void run_gemm(const __nv_bfloat16* Ahi, const __nv_bfloat16* Alo,
                            const __nv_bfloat16* Bhi, const __nv_bfloat16* Blo,
                            float* Cf, __nv_bfloat16* Chi, __nv_bfloat16* Clo,
                            int M, int Nc, int Kp,
                            const float* bias, int act,
                            const float* aggr = nullptr,
                            const float* gat_bias = nullptr,
                            const float* w2v = nullptr,
                            const float* b2v = nullptr,
                            float* outv = nullptr)
{
    dim3 grid((Nc + 127) / 128, (M + 127) / 128);
    mma_gemm_kernel<<<grid, 256, TC_SMEM>>>(Ahi, Alo, Bhi, Blo, Cf, Chi, Clo,
                                            M, Nc, Kp, bias, act, aggr, gat_bias,
                                            w2v, b2v, outv);
}

static void run_gat(const int* off, const int* csr, int N, int H, int C,
                    const float* hW, const float* att_src, const float* att_dst,
                    float* asrc, float* adst, float* out)
{
    long long warps = (long long)N * H;
    long long blocks = (warps * 32 + 255) / 256;
    att_dots_kernel<<<(unsigned)blocks, 256>>>(hW, att_src, att_dst, asrc, adst, N, H, C);
    gat_aggr_csr_kernel<<<(unsigned)blocks, 256>>>(off, csr, asrc, adst, hW, out, N, H, C);
}

extern "C" void kernel_launch(void* const* d_in, const int* in_sizes, int n_in,
                              void* d_out, int out_size)
{
    const float* x      = (const float*)d_in[0];
    const int*   ei     = (const int*)d_in[1];
    const float* enc_w1 = (const float*)d_in[2];
    const float* enc_b1 = (const float*)d_in[3];
    const float* ln1_g  = (const float*)d_in[4];
    const float* ln1_b  = (const float*)d_in[5];
    const float* enc_w2 = (const float*)d_in[6];
    const float* enc_b2 = (const float*)d_in[7];
    const float* ln2_g  = (const float*)d_in[8];
    const float* ln2_b  = (const float*)d_in[9];
    const float* w1       = (const float*)d_in[10];
    const float* att_src1 = (const float*)d_in[11];
    const float* att_dst1 = (const float*)d_in[12];
    const float* bias1    = (const float*)d_in[13];
    const float* res1_w   = (const float*)d_in[14];
    const float* res1_b   = (const float*)d_in[15];
    const float* w2       = (const float*)d_in[16];
    const float* att_src2 = (const float*)d_in[17];
    const float* att_dst2 = (const float*)d_in[18];
    const float* bias2    = (const float*)d_in[19];
    const float* res2_w   = (const float*)d_in[20];
    const float* res2_b   = (const float*)d_in[21];
    const float* w3       = (const float*)d_in[22];
    const float* att_src3 = (const float*)d_in[23];
    const float* att_dst3 = (const float*)d_in[24];
    const float* bias3    = (const float*)d_in[25];
    const float* res3_w   = (const float*)d_in[26];
    const float* res3_b   = (const float*)d_in[27];
    const float* mlp_w1   = (const float*)d_in[28];
    const float* mlp_b1   = (const float*)d_in[29];
    const float* mlp_w2   = (const float*)d_in[30];
    const float* mlp_b2   = (const float*)d_in[31];

    const int N = in_sizes[0] / GDIM;
    const int E = in_sizes[1] / 2;
    const int* srcA = ei;
    const int* dstA = ei + E;

    cudaFuncSetAttribute(mma_gemm_kernel,
                         cudaFuncAttributeMaxDynamicSharedMemorySize, TC_SMEM);

    float *t1, *henc, *A, *B, *D, *E2, *G, *Hh, *asrc, *adst;
    int *deg, *off, *pos, *csr, *blk;
    __nv_bfloat16 *b1hi, *b1lo, *b2hi, *b2lo, *whi, *wlo;
    cudaGetSymbolAddress((void**)&t1,   g_t1);
    cudaGetSymbolAddress((void**)&henc, g_henc);
    cudaGetSymbolAddress((void**)&A,    g_A);
    cudaGetSymbolAddress((void**)&B,    g_B);
    cudaGetSymbolAddress((void**)&D,    g_D);
    cudaGetSymbolAddress((void**)&E2,   g_E2);
    cudaGetSymbolAddress((void**)&G,    g_G);
    cudaGetSymbolAddress((void**)&Hh,   g_Hh);
    cudaGetSymbolAddress((void**)&asrc, g_asrc);
    cudaGetSymbolAddress((void**)&adst, g_adst);
    cudaGetSymbolAddress((void**)&deg,  g_deg);
    cudaGetSymbolAddress((void**)&off,  g_off);
    cudaGetSymbolAddress((void**)&pos,  g_pos);
    cudaGetSymbolAddress((void**)&csr,  g_csr);
    cudaGetSymbolAddress((void**)&blk,  g_blk);
    cudaGetSymbolAddress((void**)&b1hi, g_b1hi);
    cudaGetSymbolAddress((void**)&b1lo, g_b1lo);
    cudaGetSymbolAddress((void**)&b2hi, g_b2hi);
    cudaGetSymbolAddress((void**)&b2lo, g_b2lo);
    cudaGetSymbolAddress((void**)&whi,  g_whi);
    cudaGetSymbolAddress((void**)&wlo,  g_wlo);

    // ---- CSR build ----
    deg_init_kernel<<<(N + 255) / 256, 256>>>(deg, N);
    deg_hist_kernel<<<(E + 255) / 256, 256>>>(dstA, E, deg);
    scan1_kernel<<<NB_SCAN, 1024>>>(deg, off, blk, N);
    scan2_kernel<<<1, 64>>>(blk, NB_SCAN);
    scan3_kernel<<<(N + 255) / 256, 256>>>(off, blk, N);
    pos_init_kernel<<<(N + 255) / 256, 256>>>(off, pos, csr, N);
    scatter_kernel<<<(E + 255) / 256, 256>>>(srcA, dstA, E, pos, csr);

    const unsigned lnb = (N + 7) / 8;

    // ---- JointEncoder ----
    {
        int Kp = kpad64(GDIM);   // 448
        long long tot = (long long)N * (Kp >> 2);
        split_a_kernel<<<(unsigned)((tot + 255) / 256), 256>>>(x, b1hi, b1lo, N, GDIM, Kp);
        run_split_bt(enc_w1, whi, wlo, GDIM, 256, Kp);
        run_gemm(b1hi, b1lo, whi, wlo, t1, nullptr, nullptr, N, 256, Kp, enc_b1, 0);
        ln_relu_kernel<<<lnb, 256>>>(t1, ln1_g, ln1_b, b2hi, b2lo, N);

        run_split_bt(enc_w2, whi, wlo, 256, 256, 256);
        run_gemm(b2hi, b2lo, whi, wlo, henc, nullptr, nullptr, N, 256, 256, enc_b2, 0);
        ln_relu_kernel<<<lnb, 256>>>(henc, ln2_g, ln2_b, b1hi, b1lo, N);
    }

    // ---- Block 1: GAT 256 -> 4x256 (concat) ----
    {
        run_split_bt(w1, whi, wlo, 256, 1024, 256);
        run_gemm(b1hi, b1lo, whi, wlo, A, nullptr, nullptr, N, 1024, 256, nullptr, 0); // hW1
        run_gat(off, csr, N, 4, 256, A, att_src1, att_dst1, asrc, adst, B);            // aggr1
        run_split_bt(res1_w, whi, wlo, 256, 1024, 256);
        run_gemm(b1hi, b1lo, whi, wlo, nullptr, b2hi, b2lo,
                 N, 1024, 256, res1_b, 2, B, bias1);                                   // h1 -> split
    }

    // ---- Block 2: GAT 1024 -> 2x96 (concat) ----
    {
        run_split_bt(w2, whi, wlo, 1024, 192, 1024);
        run_gemm(b2hi, b2lo, whi, wlo, D, nullptr, nullptr, N, 192, 1024, nullptr, 0); // hW2
        run_gat(off, csr, N, 2, 96, D, att_src2, att_dst2, asrc, adst, E2);            // aggr2
        run_split_bt(res2_w, whi, wlo, 1024, 192, 1024);
        run_gemm(b2hi, b2lo, whi, wlo, nullptr, b1hi, b1lo,
                 N, 192, 1024, res2_b, 2, E2, bias2);                                  // h2 -> split
    }

    // ---- Block 3: GAT 192 -> 1x128 (no concat) ----
    {
        run_split_bt(w3, whi, wlo, 192, 128, 192);
        run_gemm(b1hi, b1lo, whi, wlo, G, nullptr, nullptr, N, 128, 192, nullptr, 0);  // hW3
        run_gat(off, csr, N, 1, 128, G, att_src3, att_dst3, asrc, adst, Hh);           // aggr3
        run_split_bt(res3_w, whi, wlo, 192, 128, 192);
        run_gemm(b1hi, b1lo, whi, wlo, nullptr, b2hi, b2lo,
                 N, 128, 192, res3_b, 2, Hh, bias3);                                   // h3 -> split
    }

    // ---- MLP head: one GEMM, epilogue does relu + 64->2 projection ----
    {
        run_split_bt(mlp_w1, whi, wlo, 128, 64, 128);
        run_gemm(b2hi, b2lo, whi, wlo, nullptr, nullptr, nullptr,
                 N, 64, 128, mlp_b1, 3, nullptr, nullptr,
                 mlp_w2, mlp_b2, (float*)d_out);
    }
}